// round 4
// baseline (speedup 1.0000x reference)
#include <cuda_runtime.h>

#define HID 2048
#define NH  16
#define DH  128
#define LAT 512
#define BB  2
#define TT  2048
#define BT  4096   // BB*TT
#define BH  32     // BB*NH

__device__ float g_q  [(size_t)BH * TT * DH];
__device__ float g_k  [(size_t)BH * TT * DH];
__device__ float g_v  [(size_t)BH * TT * DH];
__device__ float g_lat[(size_t)BT * LAT];
__device__ float g_att[(size_t)BT * HID];
__device__ float g_sc [(size_t)BH * TT * TT];
__device__ float g_wk2[(size_t)LAT * HID];
__device__ float g_wv2[(size_t)LAT * HID];

__device__ __forceinline__ void ffma2(unsigned long long& c,
                                      unsigned long long a,
                                      unsigned long long b) {
    asm("fma.rn.f32x2 %0, %1, %2, %0;" : "+l"(c) : "l"(a), "l"(b));
}
__device__ __forceinline__ unsigned long long dup2(float x) {
    unsigned long long r;
    asm("mov.b64 %0, {%1, %1};" : "=l"(r) : "f"(x));
    return r;
}
__device__ __forceinline__ float2 unpack2(unsigned long long v) {
    float2 r;
    asm("mov.b64 {%0, %1}, %2;" : "=f"(r.x), "=f"(r.y) : "l"(v));
    return r;
}

// Wk/Wv: [H, L, d] -> [L, H*d]
__global__ void repack_kv(const float* __restrict__ Wk,
                          const float* __restrict__ Wv) {
    int i = blockIdx.x * 256 + threadIdx.x;
    if (i >= LAT * HID) return;
    int l = i >> 11;
    int c = i & (HID - 1);
    int src = (((c >> 7) * LAT + l) << 7) + (c & 127);
    g_wk2[i] = Wk[src];
    g_wv2[i] = Wv[src];
}

// C = alpha*(A @ B(^T) + bias). 128x128 tile, BK=8, 256 thr, 8x8 microtile,
// packed f32x2 FMAs. TRANS_B: 0 -> B[K,N], 1 -> B[N,K].
// CMODE: 0 plain; 1 scatter token-rows -> [bh][t][d]; 2 gather -> [b*T+t][h*128+d]
template<int TRANS_B, int CMODE>
__global__ void __launch_bounds__(256, 2)
gemm2(const float* __restrict__ A, const float* __restrict__ B,
      const float* __restrict__ bias, float* __restrict__ C,
      int K, int lda, int ldb, int ldc,
      long long sAz, long long sBz, long long sCz, float alpha)
{
    __shared__ __align__(16) unsigned long long As2[8][130];
    __shared__ __align__(16) float              Bs [8][132];

    const int z = blockIdx.z;
    A += (long long)z * sAz;
    B += (long long)z * sBz;

    const int tid = threadIdx.x;
    const int tx = tid & 15, ty = tid >> 4;
    const int row0 = blockIdx.y * 128;
    const int col0 = blockIdx.x * 128;

    const int am = tid >> 1, ak = (tid & 1) * 4;
    const int bkn = tid >> 5, bnn = (tid & 31) * 4;   // NN map
    const int bnt = tid >> 1, bkt = (tid & 1) * 4;    // NT map

    const float* Ap = A + (long long)(row0 + am) * lda + ak;
    const float* Bp = TRANS_B
        ? (B + (long long)(col0 + bnt) * ldb + bkt)
        : (B + (long long)bkn * ldb + col0 + bnn);

    unsigned long long acc[8][4];
#pragma unroll
    for (int i = 0; i < 8; i++)
#pragma unroll
        for (int p = 0; p < 4; p++) acc[i][p] = 0ull;

    const int nt = K >> 3;
    float4 aR = *(const float4*)Ap;
    float4 bR = *(const float4*)Bp;

    for (int t = 0; t < nt; ++t) {
        As2[ak + 0][am] = dup2(aR.x);
        As2[ak + 1][am] = dup2(aR.y);
        As2[ak + 2][am] = dup2(aR.z);
        As2[ak + 3][am] = dup2(aR.w);
        if (TRANS_B) {
            Bs[bkt + 0][bnt] = bR.x;
            Bs[bkt + 1][bnt] = bR.y;
            Bs[bkt + 2][bnt] = bR.z;
            Bs[bkt + 3][bnt] = bR.w;
        } else {
            *(float4*)&Bs[bkn][bnn] = bR;
        }
        __syncthreads();

        if (t + 1 < nt) {
            Ap += 8;
            Bp += TRANS_B ? (long long)8 : (long long)8 * ldb;
            aR = *(const float4*)Ap;
            bR = *(const float4*)Bp;
        }

#pragma unroll
        for (int kk = 0; kk < 8; ++kk) {
            const unsigned long long* ar = &As2[kk][ty * 8];
            ulonglong2 a01 = *(const ulonglong2*)(ar);
            ulonglong2 a23 = *(const ulonglong2*)(ar + 2);
            ulonglong2 a45 = *(const ulonglong2*)(ar + 4);
            ulonglong2 a67 = *(const ulonglong2*)(ar + 6);
            const float* br = &Bs[kk][tx * 8];
            ulonglong2 b01 = *(const ulonglong2*)(br);
            ulonglong2 b23 = *(const ulonglong2*)(br + 4);
            unsigned long long a2[8] = {a01.x, a01.y, a23.x, a23.y,
                                        a45.x, a45.y, a67.x, a67.y};
            unsigned long long b2[4] = {b01.x, b01.y, b23.x, b23.y};
#pragma unroll
            for (int i = 0; i < 8; i++)
#pragma unroll
                for (int p = 0; p < 4; p++)
                    ffma2(acc[i][p], a2[i], b2[p]);
        }
        __syncthreads();
    }

    float bf[8];
    if (bias) {
        *(float4*)&bf[0] = *(const float4*)&bias[col0 + tx * 8];
        *(float4*)&bf[4] = *(const float4*)&bias[col0 + tx * 8 + 4];
    } else {
#pragma unroll
        for (int j = 0; j < 8; j++) bf[j] = 0.f;
    }
    const int n0 = col0 + tx * 8;
#pragma unroll
    for (int i = 0; i < 8; i++) {
        const int m = row0 + ty * 8 + i;
        float cf[8];
#pragma unroll
        for (int p = 0; p < 4; p++) {
            float2 u = unpack2(acc[i][p]);
            cf[2 * p] = u.x; cf[2 * p + 1] = u.y;
        }
        float4 o0, o1;
        o0.x = alpha * (cf[0] + bf[0]); o0.y = alpha * (cf[1] + bf[1]);
        o0.z = alpha * (cf[2] + bf[2]); o0.w = alpha * (cf[3] + bf[3]);
        o1.x = alpha * (cf[4] + bf[4]); o1.y = alpha * (cf[5] + bf[5]);
        o1.z = alpha * (cf[6] + bf[6]); o1.w = alpha * (cf[7] + bf[7]);

        long long idx;
        if (CMODE == 0) {
            idx = (long long)z * sCz + (long long)m * ldc + n0;
        } else if (CMODE == 1) {
            int b = m >> 11, t2 = m & (TT - 1);
            int h = n0 >> 7, d = n0 & 127;
            idx = (((long long)(b * NH + h)) * TT + t2) * DH + d;
        } else {
            int b = z >> 4, h = z & 15;
            idx = ((long long)(b * TT + m)) * HID + h * DH + n0;
        }
        *(float4*)&C[idx]     = o0;
        *(float4*)&C[idx + 4] = o1;
    }
}

// row softmax over 2048 elems; 1 block / row
__global__ void softmax_rows(float* __restrict__ S) {
    __shared__ float red[8];
    float4* p = (float4*)(S + (long long)blockIdx.x * TT);
    const int tid = threadIdx.x;
    float4 v0 = p[tid];
    float4 v1 = p[tid + 256];

    float mx = fmaxf(fmaxf(fmaxf(v0.x, v0.y), fmaxf(v0.z, v0.w)),
                     fmaxf(fmaxf(v1.x, v1.y), fmaxf(v1.z, v1.w)));
#pragma unroll
    for (int o = 16; o; o >>= 1) mx = fmaxf(mx, __shfl_xor_sync(~0u, mx, o));
    if ((tid & 31) == 0) red[tid >> 5] = mx;
    __syncthreads();
    mx = red[0];
#pragma unroll
    for (int i = 1; i < 8; i++) mx = fmaxf(mx, red[i]);
    __syncthreads();

    v0.x = __expf(v0.x - mx); v0.y = __expf(v0.y - mx);
    v0.z = __expf(v0.z - mx); v0.w = __expf(v0.w - mx);
    v1.x = __expf(v1.x - mx); v1.y = __expf(v1.y - mx);
    v1.z = __expf(v1.z - mx); v1.w = __expf(v1.w - mx);

    float s = v0.x + v0.y + v0.z + v0.w + v1.x + v1.y + v1.z + v1.w;
#pragma unroll
    for (int o = 16; o; o >>= 1) s += __shfl_xor_sync(~0u, s, o);
    if ((tid & 31) == 0) red[tid >> 5] = s;
    __syncthreads();
    s = red[0];
#pragma unroll
    for (int i = 1; i < 8; i++) s += red[i];

    float inv = 1.0f / s;
    v0.x *= inv; v0.y *= inv; v0.z *= inv; v0.w *= inv;
    v1.x *= inv; v1.y *= inv; v1.z *= inv; v1.w *= inv;
    p[tid] = v0;
    p[tid + 256] = v1;
}

extern "C" void kernel_launch(void* const* d_in, const int* in_sizes, int n_in,
                              void* d_out, int out_size) {
    const float* x  = (const float*)d_in[0];
    const float* Wq = (const float*)d_in[1];
    const float* bq = (const float*)d_in[2];
    const float* Wl = (const float*)d_in[3];
    const float* bl = (const float*)d_in[4];
    const float* Wk = (const float*)d_in[5];
    const float* bk = (const float*)d_in[6];
    const float* Wv = (const float*)d_in[7];
    const float* bv = (const float*)d_in[8];
    const float* Wo = (const float*)d_in[9];
    const float* bo = (const float*)d_in[10];
    float* out = (float*)d_out;

    float *qp, *kp, *vp, *lp, *ap, *sp, *wkp, *wvp;
    cudaGetSymbolAddress((void**)&qp,  g_q);
    cudaGetSymbolAddress((void**)&kp,  g_k);
    cudaGetSymbolAddress((void**)&vp,  g_v);
    cudaGetSymbolAddress((void**)&lp,  g_lat);
    cudaGetSymbolAddress((void**)&ap,  g_att);
    cudaGetSymbolAddress((void**)&sp,  g_sc);
    cudaGetSymbolAddress((void**)&wkp, g_wk2);
    cudaGetSymbolAddress((void**)&wvp, g_wv2);

    const float qscale = 0.08838834764831845f;  // 1/sqrt(128)

    // repack per-head Wk/Wv into [L, H*d]
    repack_kv<<<(LAT * HID + 255) / 256, 256>>>(Wk, Wv);

    // Q = (x@Wq + bq) * scale, scattered to [bh][t][d]
    gemm2<0, 1><<<dim3(16, 32, 1), 256>>>(x, Wq, bq, qp,
        HID, HID, HID, 0, 0, 0, 0, qscale);

    // latent = x@Wl + bl  -> [BT, LAT]
    gemm2<0, 0><<<dim3(4, 32, 1), 256>>>(x, Wl, bl, lp,
        HID, HID, LAT, LAT, 0, 0, 0, 1.f);

    // K = latent@Wk2 + bk, V = latent@Wv2 + bv, scattered to [bh][t][d]
    gemm2<0, 1><<<dim3(16, 32, 1), 256>>>(lp, wkp, bk, kp,
        LAT, LAT, HID, 0, 0, 0, 0, 1.f);
    gemm2<0, 1><<<dim3(16, 32, 1), 256>>>(lp, wvp, bv, vp,
        LAT, LAT, HID, 0, 0, 0, 0, 1.f);

    // scores[bh] = Q[bh] @ K[bh]^T  (NT, batched z=32)
    gemm2<1, 0><<<dim3(16, 16, 32), 256>>>(qp, kp, nullptr, sp,
        DH, DH, DH, TT,
        (long long)TT * DH, (long long)TT * DH, (long long)TT * TT, 1.f);

    // softmax over rows
    softmax_rows<<<BH * TT, 256>>>(sp);

    // att[bh] = P[bh] @ V[bh], gathered back to [b*T+t][h*128+d]
    gemm2<0, 2><<<dim3(1, 16, 32), 256>>>(sp, vp, nullptr, ap,
        TT, TT, DH, 0,
        (long long)TT * TT, (long long)TT * DH, 0, 1.f);

    // out = att@Wo + bo
    gemm2<0, 0><<<dim3(16, 32, 1), 256>>>(ap, Wo, bo, out,
        HID, HID, HID, HID, 0, 0, 0, 1.f);
}

// round 6
// speedup vs baseline: 2.3634x; 2.3634x over previous
#include <cuda_runtime.h>
#include <cuda_bf16.h>
#include <cstdint>

#define HID 2048
#define NH  16
#define DH  128
#define LAT 512
#define TT  2048
#define BT  4096
#define BH  32

typedef __nv_bfloat16 bf16;

// ------------------------- static scratch (256B aligned) -------------------
__device__ __align__(256) bf16 g_xh[(size_t)BT * HID],  g_xl[(size_t)BT * HID];
__device__ __align__(256) bf16 g_wqh[(size_t)HID * HID], g_wql[(size_t)HID * HID];
__device__ __align__(256) bf16 g_wlh[(size_t)LAT * HID], g_wll[(size_t)LAT * HID];
__device__ __align__(256) bf16 g_wkh[(size_t)HID * LAT], g_wkl[(size_t)HID * LAT];
__device__ __align__(256) bf16 g_wvh[(size_t)HID * LAT], g_wvl[(size_t)HID * LAT];
__device__ __align__(256) bf16 g_woh[(size_t)HID * HID], g_wol[(size_t)HID * HID];
__device__ __align__(256) bf16 g_lath[(size_t)BT * LAT], g_latl[(size_t)BT * LAT];
__device__ __align__(256) bf16 g_qh[(size_t)BH * TT * DH], g_ql[(size_t)BH * TT * DH];
__device__ __align__(256) bf16 g_kh[(size_t)BH * TT * DH], g_kl[(size_t)BH * TT * DH];
__device__ __align__(256) bf16 g_vth[(size_t)BH * TT * DH], g_vtl[(size_t)BH * TT * DH];
__device__ __align__(256) float g_sc[(size_t)BH * TT * TT];
__device__ __align__(256) bf16 g_ph[(size_t)BH * TT * TT], g_pl[(size_t)BH * TT * TT];
__device__ __align__(256) bf16 g_ath[(size_t)BT * HID],  g_atl[(size_t)BT * HID];

// ------------------------- helpers ----------------------------------------
__device__ __forceinline__ uint32_t smem_u32(const void* p) {
    uint32_t a;
    asm("{ .reg .u64 t; cvta.to.shared.u64 t, %1; cvt.u32.u64 %0, t; }"
        : "=r"(a) : "l"(p));
    return a;
}
__device__ __forceinline__ float bf16r(float x) {
    return __bfloat162float(__float2bfloat16(x));
}
__device__ __forceinline__ uint32_t pk2(float a, float b) {
    __nv_bfloat162 t = __floats2bfloat162_rn(a, b);
    return *reinterpret_cast<uint32_t*>(&t);
}
__device__ __forceinline__ void cp16(uint32_t s, const void* g) {
    asm volatile("cp.async.cg.shared.global [%0], [%1], 16;" :: "r"(s), "l"(g));
}
__device__ __forceinline__ void mma16816(float* c, const uint32_t* a,
                                         const uint32_t* b) {
    asm volatile("mma.sync.aligned.m16n8k16.row.col.f32.bf16.bf16.f32 "
        "{%0,%1,%2,%3}, {%4,%5,%6,%7}, {%8,%9}, {%0,%1,%2,%3};"
        : "+f"(c[0]), "+f"(c[1]), "+f"(c[2]), "+f"(c[3])
        : "r"(a[0]), "r"(a[1]), "r"(a[2]), "r"(a[3]), "r"(b[0]), "r"(b[1]));
}
__device__ __forceinline__ void ldsm4(uint32_t* r, uint32_t addr) {
    asm volatile("ldmatrix.sync.aligned.m8n8.x4.shared.b16 {%0,%1,%2,%3}, [%4];"
        : "=r"(r[0]), "=r"(r[1]), "=r"(r[2]), "=r"(r[3]) : "r"(addr));
}

// ------------------------- conversion kernels ------------------------------
__global__ void split_f4(const float* __restrict__ X, bf16* __restrict__ H,
                         bf16* __restrict__ L, int n4) {
    int i = blockIdx.x * 256 + threadIdx.x;
    if (i >= n4) return;
    float4 v = ((const float4*)X)[i];
    float ax = bf16r(v.x), ay = bf16r(v.y), az = bf16r(v.z), aw = bf16r(v.w);
    uint2 h, l;
    h.x = pk2(ax, ay);             h.y = pk2(az, aw);
    l.x = pk2(v.x - ax, v.y - ay); l.y = pk2(v.z - az, v.w - aw);
    *(uint2*)(H + (size_t)i * 4) = h;
    *(uint2*)(L + (size_t)i * 4) = l;
}

// W [K,N] row-major -> out [N,K] hi/lo. z-batched.
__global__ void trans_split(const float* __restrict__ W, bf16* __restrict__ OH,
                            bf16* __restrict__ OL, int K, int N,
                            long long zin, long long zout) {
    __shared__ float tile[32][33];
    W  += (size_t)blockIdx.z * zin;
    OH += (size_t)blockIdx.z * zout;
    OL += (size_t)blockIdx.z * zout;
    int n0 = blockIdx.x * 32, k0 = blockIdx.y * 32;
    int tx = threadIdx.x, ty = threadIdx.y;
#pragma unroll
    for (int j = 0; j < 32; j += 8)
        tile[ty + j][tx] = W[(size_t)(k0 + ty + j) * N + n0 + tx];
    __syncthreads();
#pragma unroll
    for (int j = 0; j < 32; j += 8) {
        float v = tile[tx][ty + j];
        float h = bf16r(v);
        size_t idx = (size_t)(n0 + ty + j) * K + k0 + tx;
        OH[idx] = __float2bfloat16(h);
        OL[idx] = __float2bfloat16(v - h);
    }
}

// ------------------------- HMMA GEMM ---------------------------------------
// C(128x128) = alpha*((Ah+Al)@(Bh+Bl)^T + bias), 3-MMA hi/lo split.
// A:[M,K] K-major, B:[N,K] K-major (bf16 hi/lo pairs). K multiple of 32.
// CMODE 0: fp32 out0[z*sCz + m*ldc + n]
//       1: split (oh,ol)[m*ldc + n]
//       2: split scatter: m=b*T+t, n=h*128+d -> [bh][t][d]
//       3: split scatter V^T:      n=h*128+d -> [bh][d][t]
//       4: split gather: z=bh, m=q, n=d -> [b*T+q][h*128+d]
// smem: 2 stages x 4 tiles (Ah,Al,Bh,Bl) of [128 rows x 32 bf16], 80B row
// stride (conflict-free ldmatrix). 81920 bytes total.
template<int CMODE>
__global__ void __launch_bounds__(256, 1)
mma_gemm(const bf16* __restrict__ Ah, const bf16* __restrict__ Al,
         const bf16* __restrict__ Bh, const bf16* __restrict__ Bl,
         const float* __restrict__ bias, float* __restrict__ out0,
         bf16* __restrict__ oh, bf16* __restrict__ ol,
         int K, int lda, int ldb, int ldc,
         long long sAz, long long sBz, long long sCz, float alpha)
{
    extern __shared__ char smem[];
    const uint32_t sb = smem_u32(smem);
    const int tid = threadIdx.x, lid = tid & 31, wid = tid >> 5;
    const int wm = wid >> 1, wn = wid & 1;
    const int z = blockIdx.z;
    const int row0 = blockIdx.y << 7, col0 = blockIdx.x << 7;

    const bf16* gsrc[4];
    gsrc[0] = Ah + (size_t)z * sAz + (size_t)row0 * lda;
    gsrc[1] = Al + (size_t)z * sAz + (size_t)row0 * lda;
    gsrc[2] = Bh + (size_t)z * sBz + (size_t)col0 * ldb;
    gsrc[3] = Bl + (size_t)z * sBz + (size_t)col0 * ldb;

    const int nt = K >> 5;

    // staging: 2048 16B-chunks/stage, 8 per thread
    auto load_stage = [&](int buf, int kt) {
#pragma unroll
        for (int i = 0; i < 8; ++i) {
            int cid = tid + (i << 8);
            int q = cid >> 9, idx = cid & 511;
            int row = idx >> 2, c = idx & 3;
            int ld = (q < 2) ? lda : ldb;
            const bf16* g = gsrc[q] + (size_t)row * ld + (kt << 5) + (c << 3);
            uint32_t s = sb + (uint32_t)(buf * 4 + q) * 10240u
                            + (uint32_t)row * 80u + ((uint32_t)c << 4);
            cp16(s, g);
        }
        asm volatile("cp.async.commit_group;" ::: "memory");
    };

    float acc[2][8][4];
#pragma unroll
    for (int mi = 0; mi < 2; ++mi)
#pragma unroll
        for (int nj = 0; nj < 8; ++nj)
#pragma unroll
            for (int p = 0; p < 4; ++p) acc[mi][nj][p] = 0.f;

    load_stage(0, 0);
    if (nt > 1) load_stage(1, 1);

    const int rowA = lid & 15;
    const int cA   = lid >> 4;
    const int rowB = (lid & 7) + ((lid >> 4) << 3);
    const int cB   = (lid >> 3) & 1;

    for (int t = 0; t < nt; ++t) {
        if (t + 1 < nt)
            asm volatile("cp.async.wait_group 1;" ::: "memory");
        else
            asm volatile("cp.async.wait_group 0;" ::: "memory");
        __syncthreads();
        const uint32_t st = sb + (uint32_t)(t & 1) * 40960u;

#pragma unroll
        for (int ks = 0; ks < 2; ++ks) {
            uint32_t a[2][2][4];   // [mi][hi/lo]
#pragma unroll
            for (int mi = 0; mi < 2; ++mi)
#pragma unroll
                for (int hh = 0; hh < 2; ++hh) {
                    uint32_t addr = st + (uint32_t)hh * 10240u
                        + (uint32_t)(wm * 32 + mi * 16 + rowA) * 80u
                        + (uint32_t)(ks * 2 + cA) * 16u;
                    ldsm4(a[mi][hh], addr);
                }
#pragma unroll
            for (int nj = 0; nj < 4; ++nj) {
                uint32_t bh2[4], bl2[4];
                uint32_t ab = st + 2u * 10240u
                    + (uint32_t)(wn * 64 + nj * 16 + rowB) * 80u
                    + (uint32_t)(ks * 2 + cB) * 16u;
                ldsm4(bh2, ab);
                ldsm4(bl2, ab + 10240u);
#pragma unroll
                for (int mi = 0; mi < 2; ++mi)
#pragma unroll
                    for (int p = 0; p < 2; ++p) {
                        float* c = acc[mi][nj * 2 + p];
                        mma16816(c, a[mi][0], bh2 + 2 * p);  // Ah*Bh
                        mma16816(c, a[mi][0], bl2 + 2 * p);  // Ah*Bl
                        mma16816(c, a[mi][1], bh2 + 2 * p);  // Al*Bh
                    }
            }
        }
        __syncthreads();
        if (t + 2 < nt) load_stage(t & 1, t + 2);
    }

    // ------------------------- epilogue -----------------------------------
    const int g = lid >> 2, tig = lid & 3;
#pragma unroll
    for (int mi = 0; mi < 2; ++mi)
#pragma unroll
    for (int hh = 0; hh < 2; ++hh) {
        const int m = row0 + wm * 32 + mi * 16 + g + hh * 8;
#pragma unroll
        for (int nj = 0; nj < 8; ++nj) {
            const int n = col0 + wn * 64 + nj * 8 + tig * 2;
            float v0 = acc[mi][nj][hh * 2 + 0];
            float v1 = acc[mi][nj][hh * 2 + 1];
            if (bias) { v0 += bias[n]; v1 += bias[n + 1]; }
            v0 *= alpha; v1 *= alpha;
            if (CMODE == 0) {
                *(float2*)(out0 + (size_t)z * sCz + (size_t)m * ldc + n) =
                    make_float2(v0, v1);
            } else if (CMODE == 3) {
                int b = m >> 11, t2 = m & (TT - 1);
                size_t i0 = ((size_t)((b << 4) + (n >> 7)) * DH + (n & 127)) * TT + t2;
                float h0 = bf16r(v0), h1 = bf16r(v1);
                oh[i0]      = __float2bfloat16(h0);
                ol[i0]      = __float2bfloat16(v0 - h0);
                oh[i0 + TT] = __float2bfloat16(h1);
                ol[i0 + TT] = __float2bfloat16(v1 - h1);
            } else {
                size_t base;
                if (CMODE == 1) {
                    base = (size_t)m * ldc + n;
                } else if (CMODE == 2) {
                    int b = m >> 11, t2 = m & (TT - 1);
                    base = ((size_t)((b << 4) + (n >> 7)) * TT + t2) * DH + (n & 127);
                } else { // 4
                    int b = z >> 4, h = z & 15;
                    base = ((size_t)(b * TT + m)) * HID + (h << 7) + n;
                }
                float h0 = bf16r(v0), h1 = bf16r(v1);
                *(uint32_t*)(oh + base) = pk2(h0, h1);
                *(uint32_t*)(ol + base) = pk2(v0 - h0, v1 - h1);
            }
        }
    }
}

// ------------------------- softmax + split ---------------------------------
__global__ void softmax_split(const float* __restrict__ S, bf16* __restrict__ PH,
                              bf16* __restrict__ PL) {
    __shared__ float red[8];
    const float4* p = (const float4*)(S + (size_t)blockIdx.x * TT);
    const int tid = threadIdx.x;
    float4 v0 = p[tid], v1 = p[tid + 256];

    float mx = fmaxf(fmaxf(fmaxf(v0.x, v0.y), fmaxf(v0.z, v0.w)),
                     fmaxf(fmaxf(v1.x, v1.y), fmaxf(v1.z, v1.w)));
#pragma unroll
    for (int o = 16; o; o >>= 1) mx = fmaxf(mx, __shfl_xor_sync(~0u, mx, o));
    if ((tid & 31) == 0) red[tid >> 5] = mx;
    __syncthreads();
    mx = red[0];
#pragma unroll
    for (int i = 1; i < 8; i++) mx = fmaxf(mx, red[i]);
    __syncthreads();

    v0.x = __expf(v0.x - mx); v0.y = __expf(v0.y - mx);
    v0.z = __expf(v0.z - mx); v0.w = __expf(v0.w - mx);
    v1.x = __expf(v1.x - mx); v1.y = __expf(v1.y - mx);
    v1.z = __expf(v1.z - mx); v1.w = __expf(v1.w - mx);
    float s = v0.x + v0.y + v0.z + v0.w + v1.x + v1.y + v1.z + v1.w;
#pragma unroll
    for (int o = 16; o; o >>= 1) s += __shfl_xor_sync(~0u, s, o);
    if ((tid & 31) == 0) red[tid >> 5] = s;
    __syncthreads();
    s = red[0];
#pragma unroll
    for (int i = 1; i < 8; i++) s += red[i];
    float inv = 1.0f / s;

    size_t base = (size_t)blockIdx.x * TT;
#pragma unroll
    for (int half = 0; half < 2; ++half) {
        float4 v = half ? v1 : v0;
        v.x *= inv; v.y *= inv; v.z *= inv; v.w *= inv;
        float ax = bf16r(v.x), ay = bf16r(v.y), az = bf16r(v.z), aw = bf16r(v.w);
        uint2 h, l;
        h.x = pk2(ax, ay);             h.y = pk2(az, aw);
        l.x = pk2(v.x - ax, v.y - ay); l.y = pk2(v.z - az, v.w - aw);
        size_t off = base + (half ? 1024 : 0) + (size_t)tid * 4;
        *(uint2*)(PH + off) = h;
        *(uint2*)(PL + off) = l;
    }
}

// ------------------------- launcher ----------------------------------------
extern "C" void kernel_launch(void* const* d_in, const int* in_sizes, int n_in,
                              void* d_out, int out_size) {
    const float* x  = (const float*)d_in[0];
    const float* Wq = (const float*)d_in[1];
    const float* bq = (const float*)d_in[2];
    const float* Wl = (const float*)d_in[3];
    const float* bl = (const float*)d_in[4];
    const float* Wk = (const float*)d_in[5];
    const float* bk = (const float*)d_in[6];
    const float* Wv = (const float*)d_in[7];
    const float* bv = (const float*)d_in[8];
    const float* Wo = (const float*)d_in[9];
    const float* bo = (const float*)d_in[10];
    float* out = (float*)d_out;

    bf16 *xh, *xl, *wqh, *wql, *wlh, *wll, *wkh, *wkl, *wvh, *wvl, *woh, *wol;
    bf16 *lath, *latl, *qh, *ql, *kh, *kl, *vth, *vtl, *ph, *pl, *ath, *atl;
    float* sp;
    cudaGetSymbolAddress((void**)&xh, g_xh);   cudaGetSymbolAddress((void**)&xl, g_xl);
    cudaGetSymbolAddress((void**)&wqh, g_wqh); cudaGetSymbolAddress((void**)&wql, g_wql);
    cudaGetSymbolAddress((void**)&wlh, g_wlh); cudaGetSymbolAddress((void**)&wll, g_wll);
    cudaGetSymbolAddress((void**)&wkh, g_wkh); cudaGetSymbolAddress((void**)&wkl, g_wkl);
    cudaGetSymbolAddress((void**)&wvh, g_wvh); cudaGetSymbolAddress((void**)&wvl, g_wvl);
    cudaGetSymbolAddress((void**)&woh, g_woh); cudaGetSymbolAddress((void**)&wol, g_wol);
    cudaGetSymbolAddress((void**)&lath, g_lath); cudaGetSymbolAddress((void**)&latl, g_latl);
    cudaGetSymbolAddress((void**)&qh, g_qh);   cudaGetSymbolAddress((void**)&ql, g_ql);
    cudaGetSymbolAddress((void**)&kh, g_kh);   cudaGetSymbolAddress((void**)&kl, g_kl);
    cudaGetSymbolAddress((void**)&vth, g_vth); cudaGetSymbolAddress((void**)&vtl, g_vtl);
    cudaGetSymbolAddress((void**)&ph, g_ph);   cudaGetSymbolAddress((void**)&pl, g_pl);
    cudaGetSymbolAddress((void**)&ath, g_ath); cudaGetSymbolAddress((void**)&atl, g_atl);
    cudaGetSymbolAddress((void**)&sp, g_sc);

    const int SMEM = 81920;  // 2 stages x 4 tiles x 10240B
    cudaFuncSetAttribute(mma_gemm<0>, cudaFuncAttributeMaxDynamicSharedMemorySize, SMEM);
    cudaFuncSetAttribute(mma_gemm<1>, cudaFuncAttributeMaxDynamicSharedMemorySize, SMEM);
    cudaFuncSetAttribute(mma_gemm<2>, cudaFuncAttributeMaxDynamicSharedMemorySize, SMEM);
    cudaFuncSetAttribute(mma_gemm<3>, cudaFuncAttributeMaxDynamicSharedMemorySize, SMEM);
    cudaFuncSetAttribute(mma_gemm<4>, cudaFuncAttributeMaxDynamicSharedMemorySize, SMEM);

    const float qscale = 0.08838834764831845f; // 1/sqrt(128)
    dim3 tb(32, 8);

    // operand prep
    split_f4<<<(BT * HID / 4 + 255) / 256, 256>>>(x, xh, xl, BT * HID / 4);
    trans_split<<<dim3(HID / 32, HID / 32, 1), tb>>>(Wq, wqh, wql, HID, HID, 0, 0);
    trans_split<<<dim3(LAT / 32, HID / 32, 1), tb>>>(Wl, wlh, wll, HID, LAT, 0, 0);
    trans_split<<<dim3(DH / 32, LAT / 32, NH), tb>>>(Wk, wkh, wkl, LAT, DH,
        (long long)LAT * DH, (long long)DH * LAT);
    trans_split<<<dim3(DH / 32, LAT / 32, NH), tb>>>(Wv, wvh, wvl, LAT, DH,
        (long long)LAT * DH, (long long)DH * LAT);
    trans_split<<<dim3(HID / 32, HID / 32, 1), tb>>>(Wo, woh, wol, HID, HID, 0, 0);

    // Q = (x@Wq+bq)*scale -> [bh][t][d]
    mma_gemm<2><<<dim3(16, 32, 1), 256, SMEM>>>(xh, xl, wqh, wql, bq,
        nullptr, qh, ql, HID, HID, HID, 0, 0, 0, 0, qscale);
    // latent = x@Wl+bl -> [BT,LAT]
    mma_gemm<1><<<dim3(4, 32, 1), 256, SMEM>>>(xh, xl, wlh, wll, bl,
        nullptr, lath, latl, HID, HID, HID, LAT, 0, 0, 0, 1.f);
    // K = latent@Wk'+bk -> [bh][t][d]
    mma_gemm<2><<<dim3(16, 32, 1), 256, SMEM>>>(lath, latl, wkh, wkl, bk,
        nullptr, kh, kl, LAT, LAT, LAT, 0, 0, 0, 0, 1.f);
    // V = latent@Wv'+bv -> [bh][d][t]  (transposed for PV)
    mma_gemm<3><<<dim3(16, 32, 1), 256, SMEM>>>(lath, latl, wvh, wvl, bv,
        nullptr, vth, vtl, LAT, LAT, LAT, 0, 0, 0, 0, 1.f);
    // scores[bh] = Q@K^T (fp32)
    mma_gemm<0><<<dim3(16, 16, 32), 256, SMEM>>>(qh, ql, kh, kl, nullptr,
        sp, nullptr, nullptr, DH, DH, DH, TT,
        (long long)TT * DH, (long long)TT * DH, (long long)TT * TT, 1.f);
    // P = softmax(scores) -> hi/lo
    softmax_split<<<BH * TT, 256>>>(sp, ph, pl);
    // att[bh] = P@V -> [b*T+q][h*128+d]
    mma_gemm<4><<<dim3(1, 16, 32), 256, SMEM>>>(ph, pl, vth, vtl, nullptr,
        nullptr, ath, atl, TT, TT, TT, 0,
        (long long)TT * TT, (long long)DH * TT, 0, 1.f);
    // out = att@Wo+bo (fp32)
    mma_gemm<0><<<dim3(16, 32, 1), 256, SMEM>>>(ath, atl, woh, wol, bo,
        out, nullptr, nullptr, HID, HID, HID, HID, 0, 0, 0, 1.f);
}

// round 7
// speedup vs baseline: 3.2036x; 1.3555x over previous
#include <cuda_runtime.h>
#include <cuda_bf16.h>
#include <cstdint>

#define HID 2048
#define NH  16
#define DH  128
#define LAT 512
#define TT  2048
#define BT  4096
#define BH  32

typedef __nv_bfloat16 bf16;

// ------------------------- static scratch ----------------------------------
__device__ __align__(256) bf16 g_xh[(size_t)BT * HID],  g_xl[(size_t)BT * HID];
__device__ __align__(256) bf16 g_wqh[(size_t)HID * HID], g_wql[(size_t)HID * HID];
__device__ __align__(256) bf16 g_wlh[(size_t)LAT * HID], g_wll[(size_t)LAT * HID];
__device__ __align__(256) bf16 g_wkh[(size_t)HID * LAT], g_wkl[(size_t)HID * LAT];
__device__ __align__(256) bf16 g_wvh[(size_t)HID * LAT], g_wvl[(size_t)HID * LAT];
__device__ __align__(256) bf16 g_woh[(size_t)HID * HID], g_wol[(size_t)HID * HID];
__device__ __align__(256) bf16 g_lath[(size_t)BT * LAT], g_latl[(size_t)BT * LAT];
__device__ __align__(256) bf16 g_qh[(size_t)BH * TT * DH], g_ql[(size_t)BH * TT * DH];
__device__ __align__(256) bf16 g_kh[(size_t)BH * TT * DH], g_kl[(size_t)BH * TT * DH];
__device__ __align__(256) bf16 g_vth[(size_t)BH * TT * DH], g_vtl[(size_t)BH * TT * DH];
__device__ __align__(256) bf16 g_ath[(size_t)BT * HID],  g_atl[(size_t)BT * HID];

// ------------------------- helpers ----------------------------------------
__device__ __forceinline__ uint32_t smem_u32(const void* p) {
    uint32_t a;
    asm("{ .reg .u64 t; cvta.to.shared.u64 t, %1; cvt.u32.u64 %0, t; }"
        : "=r"(a) : "l"(p));
    return a;
}
__device__ __forceinline__ float bf16r(float x) {
    return __bfloat162float(__float2bfloat16(x));
}
__device__ __forceinline__ uint32_t pk2(float a, float b) {
    __nv_bfloat162 t = __floats2bfloat162_rn(a, b);
    return *reinterpret_cast<uint32_t*>(&t);
}
__device__ __forceinline__ void cp16(uint32_t s, const void* g) {
    asm volatile("cp.async.cg.shared.global [%0], [%1], 16;" :: "r"(s), "l"(g));
}
__device__ __forceinline__ void mma16816(float* c, const uint32_t* a,
                                         const uint32_t* b) {
    asm volatile("mma.sync.aligned.m16n8k16.row.col.f32.bf16.bf16.f32 "
        "{%0,%1,%2,%3}, {%4,%5,%6,%7}, {%8,%9}, {%0,%1,%2,%3};"
        : "+f"(c[0]), "+f"(c[1]), "+f"(c[2]), "+f"(c[3])
        : "r"(a[0]), "r"(a[1]), "r"(a[2]), "r"(a[3]), "r"(b[0]), "r"(b[1]));
}
__device__ __forceinline__ void ldsm4(uint32_t* r, uint32_t addr) {
    asm volatile("ldmatrix.sync.aligned.m8n8.x4.shared.b16 {%0,%1,%2,%3}, [%4];"
        : "=r"(r[0]), "=r"(r[1]), "=r"(r[2]), "=r"(r[3]) : "r"(addr));
}

// ------------------------- conversion kernels ------------------------------
__global__ void split_f4(const float* __restrict__ X, bf16* __restrict__ H,
                         bf16* __restrict__ L, int n4) {
    int i = blockIdx.x * 256 + threadIdx.x;
    if (i >= n4) return;
    float4 v = ((const float4*)X)[i];
    float ax = bf16r(v.x), ay = bf16r(v.y), az = bf16r(v.z), aw = bf16r(v.w);
    uint2 h, l;
    h.x = pk2(ax, ay);             h.y = pk2(az, aw);
    l.x = pk2(v.x - ax, v.y - ay); l.y = pk2(v.z - az, v.w - aw);
    *(uint2*)(H + (size_t)i * 4) = h;
    *(uint2*)(L + (size_t)i * 4) = l;
}

// W [K,N] row-major -> out [N,K] hi/lo. z-batched.
__global__ void trans_split(const float* __restrict__ W, bf16* __restrict__ OH,
                            bf16* __restrict__ OL, int K, int N,
                            long long zin, long long zout) {
    __shared__ float tile[32][33];
    W  += (size_t)blockIdx.z * zin;
    OH += (size_t)blockIdx.z * zout;
    OL += (size_t)blockIdx.z * zout;
    int n0 = blockIdx.x * 32, k0 = blockIdx.y * 32;
    int tx = threadIdx.x, ty = threadIdx.y;
#pragma unroll
    for (int j = 0; j < 32; j += 8)
        tile[ty + j][tx] = W[(size_t)(k0 + ty + j) * N + n0 + tx];
    __syncthreads();
#pragma unroll
    for (int j = 0; j < 32; j += 8) {
        float v = tile[tx][ty + j];
        float h = bf16r(v);
        size_t idx = (size_t)(n0 + ty + j) * K + k0 + tx;
        OH[idx] = __float2bfloat16(h);
        OL[idx] = __float2bfloat16(v - h);
    }
}

// ------------------------- HMMA GEMM (projections) -------------------------
// C(128x128) = alpha*((Ah+Al)@(Bh+Bl)^T + bias), 3-MMA hi/lo split.
// CMODE 0: fp32 out0;  1: split plain;  2: split scatter [bh][t][d];
//       3: split scatter V^T [bh][d][t]
template<int CMODE>
__global__ void __launch_bounds__(256, 1)
mma_gemm(const bf16* __restrict__ Ah, const bf16* __restrict__ Al,
         const bf16* __restrict__ Bh, const bf16* __restrict__ Bl,
         const float* __restrict__ bias, float* __restrict__ out0,
         bf16* __restrict__ oh, bf16* __restrict__ ol,
         int K, int lda, int ldb, int ldc,
         long long sAz, long long sBz, long long sCz, float alpha)
{
    extern __shared__ char smem[];
    const uint32_t sb = smem_u32(smem);
    const int tid = threadIdx.x, lid = tid & 31, wid = tid >> 5;
    const int wm = wid >> 1, wn = wid & 1;
    const int z = blockIdx.z;
    const int row0 = blockIdx.y << 7, col0 = blockIdx.x << 7;

    const bf16* gsrc[4];
    gsrc[0] = Ah + (size_t)z * sAz + (size_t)row0 * lda;
    gsrc[1] = Al + (size_t)z * sAz + (size_t)row0 * lda;
    gsrc[2] = Bh + (size_t)z * sBz + (size_t)col0 * ldb;
    gsrc[3] = Bl + (size_t)z * sBz + (size_t)col0 * ldb;

    const int nt = K >> 5;

    auto load_stage = [&](int buf, int kt) {
#pragma unroll
        for (int i = 0; i < 8; ++i) {
            int cid = tid + (i << 8);
            int q = cid >> 9, idx = cid & 511;
            int row = idx >> 2, c = idx & 3;
            int ld = (q < 2) ? lda : ldb;
            const bf16* g = gsrc[q] + (size_t)row * ld + (kt << 5) + (c << 3);
            uint32_t s = sb + (uint32_t)(buf * 4 + q) * 10240u
                            + (uint32_t)row * 80u + ((uint32_t)c << 4);
            cp16(s, g);
        }
        asm volatile("cp.async.commit_group;" ::: "memory");
    };

    float acc[2][8][4];
#pragma unroll
    for (int mi = 0; mi < 2; ++mi)
#pragma unroll
        for (int nj = 0; nj < 8; ++nj)
#pragma unroll
            for (int p = 0; p < 4; ++p) acc[mi][nj][p] = 0.f;

    load_stage(0, 0);
    if (nt > 1) load_stage(1, 1);

    const int rowA = lid & 15;
    const int cA   = lid >> 4;
    const int rowB = (lid & 7) + ((lid >> 4) << 3);
    const int cB   = (lid >> 3) & 1;

    for (int t = 0; t < nt; ++t) {
        if (t + 1 < nt)
            asm volatile("cp.async.wait_group 1;" ::: "memory");
        else
            asm volatile("cp.async.wait_group 0;" ::: "memory");
        __syncthreads();
        const uint32_t st = sb + (uint32_t)(t & 1) * 40960u;

#pragma unroll
        for (int ks = 0; ks < 2; ++ks) {
            uint32_t a[2][2][4];
#pragma unroll
            for (int mi = 0; mi < 2; ++mi)
#pragma unroll
                for (int hh = 0; hh < 2; ++hh) {
                    uint32_t addr = st + (uint32_t)hh * 10240u
                        + (uint32_t)(wm * 32 + mi * 16 + rowA) * 80u
                        + (uint32_t)(ks * 2 + cA) * 16u;
                    ldsm4(a[mi][hh], addr);
                }
#pragma unroll
            for (int nj = 0; nj < 4; ++nj) {
                uint32_t bh2[4], bl2[4];
                uint32_t ab = st + 2u * 10240u
                    + (uint32_t)(wn * 64 + nj * 16 + rowB) * 80u
                    + (uint32_t)(ks * 2 + cB) * 16u;
                ldsm4(bh2, ab);
                ldsm4(bl2, ab + 10240u);
#pragma unroll
                for (int mi = 0; mi < 2; ++mi)
#pragma unroll
                    for (int p = 0; p < 2; ++p) {
                        float* c = acc[mi][nj * 2 + p];
                        mma16816(c, a[mi][0], bh2 + 2 * p);
                        mma16816(c, a[mi][0], bl2 + 2 * p);
                        mma16816(c, a[mi][1], bh2 + 2 * p);
                    }
            }
        }
        __syncthreads();
        if (t + 2 < nt) load_stage(t & 1, t + 2);
    }

    const int g = lid >> 2, tig = lid & 3;
#pragma unroll
    for (int mi = 0; mi < 2; ++mi)
#pragma unroll
    for (int hh = 0; hh < 2; ++hh) {
        const int m = row0 + wm * 32 + mi * 16 + g + hh * 8;
#pragma unroll
        for (int nj = 0; nj < 8; ++nj) {
            const int n = col0 + wn * 64 + nj * 8 + tig * 2;
            float v0 = acc[mi][nj][hh * 2 + 0];
            float v1 = acc[mi][nj][hh * 2 + 1];
            if (bias) { v0 += bias[n]; v1 += bias[n + 1]; }
            v0 *= alpha; v1 *= alpha;
            if (CMODE == 0) {
                *(float2*)(out0 + (size_t)z * sCz + (size_t)m * ldc + n) =
                    make_float2(v0, v1);
            } else if (CMODE == 3) {
                int b = m >> 11, t2 = m & (TT - 1);
                size_t i0 = ((size_t)((b << 4) + (n >> 7)) * DH + (n & 127)) * TT + t2;
                float h0 = bf16r(v0), h1 = bf16r(v1);
                oh[i0]      = __float2bfloat16(h0);
                ol[i0]      = __float2bfloat16(v0 - h0);
                oh[i0 + TT] = __float2bfloat16(h1);
                ol[i0 + TT] = __float2bfloat16(v1 - h1);
            } else {
                size_t base;
                if (CMODE == 1) {
                    base = (size_t)m * ldc + n;
                } else { // 2
                    int b = m >> 11, t2 = m & (TT - 1);
                    base = ((size_t)((b << 4) + (n >> 7)) * TT + t2) * DH + (n & 127);
                }
                float h0 = bf16r(v0), h1 = bf16r(v1);
                *(uint32_t*)(oh + base) = pk2(h0, h1);
                *(uint32_t*)(ol + base) = pk2(v0 - h0, v1 - h1);
            }
        }
    }
}

// ------------------------- fused flash attention ---------------------------
// CTA: 128 q-rows of one (b,h). 8 warps x 16 q-rows. KV chunks of 64,
// double-buffered cp.async. S = Q@K^T 3-split; P single-bf16; O += P@V.
// smem stage: KH[64x272B] KL[64x272B] VT[128x144B] = 53248 B; x2 stages.
#define BKV  64
#define NCH  (TT / BKV)
#define KROW 272u
#define VROW 144u
#define KLOFF 17408u
#define VOFF  34816u
#define STSTR 53248u

__global__ void __launch_bounds__(256, 1)
flash_attn(const bf16* __restrict__ Qh, const bf16* __restrict__ Ql,
           const bf16* __restrict__ Kh, const bf16* __restrict__ Kl,
           const bf16* __restrict__ Vt,
           bf16* __restrict__ oh, bf16* __restrict__ ol)
{
    extern __shared__ char smem[];
    const uint32_t sb = smem_u32(smem);
    const int tid = threadIdx.x, lid = tid & 31, wid = tid >> 5;
    const int bh = blockIdx.y;
    const int q0 = blockIdx.x << 7;

    const bf16* qhb = Qh + ((size_t)bh * TT + q0) * DH;
    const bf16* qlb = Ql + ((size_t)bh * TT + q0) * DH;
    const bf16* khb = Kh + (size_t)bh * TT * DH;
    const bf16* klb = Kl + (size_t)bh * TT * DH;
    const bf16* vtb = Vt + (size_t)bh * DH * TT;

    // ---- stage Q tiles (hi in stage0 area, lo in stage1 area) ----
#pragma unroll
    for (int j = 0; j < 8; ++j) {
        int cid = tid + (j << 8);           // 0..2047
        int row = cid >> 4, c = cid & 15;
        cp16(sb + (uint32_t)row * KROW + ((uint32_t)c << 4),
             qhb + (size_t)row * DH + (c << 3));
        cp16(sb + STSTR + (uint32_t)row * KROW + ((uint32_t)c << 4),
             qlb + (size_t)row * DH + (c << 3));
    }
    asm volatile("cp.async.commit_group;" ::: "memory");
    asm volatile("cp.async.wait_group 0;" ::: "memory");
    __syncthreads();

    const int rowA = lid & 15, cA = lid >> 4;
    const int rowB = (lid & 7) + ((lid >> 4) << 3), cB = (lid >> 3) & 1;

    uint32_t qfh[8][4], qfl[8][4];
#pragma unroll
    for (int kd = 0; kd < 8; ++kd) {
        uint32_t addr = sb + (uint32_t)(wid * 16 + rowA) * KROW
                           + (uint32_t)(kd * 32 + cA * 16);
        ldsm4(qfh[kd], addr);
        ldsm4(qfl[kd], addr + STSTR);
    }
    __syncthreads();

    auto load_kv = [&](int buf, int i) {
        uint32_t s0 = sb + (uint32_t)buf * STSTR;
#pragma unroll
        for (int j = 0; j < 4; ++j) {
            int cid = tid + (j << 8);       // 0..1023
            int row = cid >> 4, c = cid & 15;
            size_t go = (size_t)(i * BKV + row) * DH + (c << 3);
            cp16(s0 + (uint32_t)row * KROW + ((uint32_t)c << 4), khb + go);
            cp16(s0 + KLOFF + (uint32_t)row * KROW + ((uint32_t)c << 4), klb + go);
        }
#pragma unroll
        for (int j = 0; j < 4; ++j) {
            int cid = tid + (j << 8);
            int row = cid >> 3, c = cid & 7;
            cp16(s0 + VOFF + (uint32_t)row * VROW + ((uint32_t)c << 4),
                 vtb + (size_t)row * TT + i * BKV + (c << 3));
        }
        asm volatile("cp.async.commit_group;" ::: "memory");
    };

    float o[16][4];
#pragma unroll
    for (int dj = 0; dj < 16; ++dj)
#pragma unroll
        for (int p = 0; p < 4; ++p) o[dj][p] = 0.f;
    float m0 = -1e30f, m1 = -1e30f, l0 = 0.f, l1 = 0.f;

    load_kv(0, 0);
    load_kv(1, 1);

    for (int i = 0; i < NCH; ++i) {
        if (i + 1 < NCH) asm volatile("cp.async.wait_group 1;" ::: "memory");
        else             asm volatile("cp.async.wait_group 0;" ::: "memory");
        __syncthreads();
        const uint32_t st = sb + (uint32_t)(i & 1) * STSTR;

        // ---- S = Q @ K^T (3-split) ----
        float s[8][4];
#pragma unroll
        for (int nj = 0; nj < 8; ++nj)
#pragma unroll
            for (int p = 0; p < 4; ++p) s[nj][p] = 0.f;
#pragma unroll
        for (int kd = 0; kd < 8; ++kd) {
#pragma unroll
            for (int g2 = 0; g2 < 4; ++g2) {
                uint32_t kf[4], kfl[4];
                uint32_t ab = st + (uint32_t)(g2 * 16 + rowB) * KROW
                                 + (uint32_t)(kd * 32 + cB * 16);
                ldsm4(kf, ab);
                ldsm4(kfl, ab + KLOFF);
#pragma unroll
                for (int p = 0; p < 2; ++p) {
                    float* c = s[g2 * 2 + p];
                    mma16816(c, qfh[kd], kf + 2 * p);
                    mma16816(c, qfh[kd], kfl + 2 * p);
                    mma16816(c, qfl[kd], kf + 2 * p);
                }
            }
        }

        // ---- online softmax (rows g and g+8) ----
        float mx0 = s[0][0], mx1 = s[0][2];
#pragma unroll
        for (int nj = 0; nj < 8; ++nj) {
            mx0 = fmaxf(mx0, fmaxf(s[nj][0], s[nj][1]));
            mx1 = fmaxf(mx1, fmaxf(s[nj][2], s[nj][3]));
        }
        mx0 = fmaxf(mx0, __shfl_xor_sync(~0u, mx0, 1));
        mx0 = fmaxf(mx0, __shfl_xor_sync(~0u, mx0, 2));
        mx1 = fmaxf(mx1, __shfl_xor_sync(~0u, mx1, 1));
        mx1 = fmaxf(mx1, __shfl_xor_sync(~0u, mx1, 2));
        float mn0 = fmaxf(m0, mx0), mn1 = fmaxf(m1, mx1);
        float es0 = __expf(m0 - mn0), es1 = __expf(m1 - mn1);
        m0 = mn0; m1 = mn1;
        l0 *= es0; l1 *= es1;
#pragma unroll
        for (int dj = 0; dj < 16; ++dj) {
            o[dj][0] *= es0; o[dj][1] *= es0;
            o[dj][2] *= es1; o[dj][3] *= es1;
        }
        float sum0 = 0.f, sum1 = 0.f;
#pragma unroll
        for (int nj = 0; nj < 8; ++nj) {
            s[nj][0] = __expf(s[nj][0] - m0);
            s[nj][1] = __expf(s[nj][1] - m0);
            s[nj][2] = __expf(s[nj][2] - m1);
            s[nj][3] = __expf(s[nj][3] - m1);
            sum0 += s[nj][0] + s[nj][1];
            sum1 += s[nj][2] + s[nj][3];
        }
        sum0 += __shfl_xor_sync(~0u, sum0, 1);
        sum0 += __shfl_xor_sync(~0u, sum0, 2);
        sum1 += __shfl_xor_sync(~0u, sum1, 1);
        sum1 += __shfl_xor_sync(~0u, sum1, 2);
        l0 += sum0; l1 += sum1;

        // ---- pack P (accumulator layout == A-fragment layout) ----
        uint32_t ap[4][4];
#pragma unroll
        for (int kt = 0; kt < 4; ++kt) {
            ap[kt][0] = pk2(s[2 * kt][0],     s[2 * kt][1]);
            ap[kt][1] = pk2(s[2 * kt][2],     s[2 * kt][3]);
            ap[kt][2] = pk2(s[2 * kt + 1][0], s[2 * kt + 1][1]);
            ap[kt][3] = pk2(s[2 * kt + 1][2], s[2 * kt + 1][3]);
        }

        // ---- O += P @ V ----
#pragma unroll
        for (int kt = 0; kt < 4; ++kt) {
#pragma unroll
            for (int dg = 0; dg < 8; ++dg) {
                uint32_t vf[4];
                uint32_t ab = st + VOFF + (uint32_t)(dg * 16 + rowB) * VROW
                                 + (uint32_t)(kt * 32 + cB * 16);
                ldsm4(vf, ab);
                mma16816(o[dg * 2 + 0], ap[kt], vf);
                mma16816(o[dg * 2 + 1], ap[kt], vf + 2);
            }
        }
        __syncthreads();
        if (i + 2 < NCH) load_kv(i & 1, i + 2);
    }

    // ---- epilogue: normalize, split, gather to [b*T+q][h*128+d] ----
    float inv0 = 1.f / l0, inv1 = 1.f / l1;
    const int b = bh >> 4, h = bh & 15;
    const int g = lid >> 2, tig = lid & 3;
    const int mrow = q0 + wid * 16 + g;
#pragma unroll
    for (int dj = 0; dj < 16; ++dj) {
        int n = (h << 7) + dj * 8 + tig * 2;
        float v0 = o[dj][0] * inv0, v1 = o[dj][1] * inv0;
        float v2 = o[dj][2] * inv1, v3 = o[dj][3] * inv1;
        size_t b0 = (size_t)(b * TT + mrow) * HID + n;
        size_t b1 = (size_t)(b * TT + mrow + 8) * HID + n;
        float h0 = bf16r(v0), h1 = bf16r(v1), h2 = bf16r(v2), h3 = bf16r(v3);
        *(uint32_t*)(oh + b0) = pk2(h0, h1);
        *(uint32_t*)(ol + b0) = pk2(v0 - h0, v1 - h1);
        *(uint32_t*)(oh + b1) = pk2(h2, h3);
        *(uint32_t*)(ol + b1) = pk2(v2 - h2, v3 - h3);
    }
}

// ------------------------- launcher ----------------------------------------
extern "C" void kernel_launch(void* const* d_in, const int* in_sizes, int n_in,
                              void* d_out, int out_size) {
    const float* x  = (const float*)d_in[0];
    const float* Wq = (const float*)d_in[1];
    const float* bq = (const float*)d_in[2];
    const float* Wl = (const float*)d_in[3];
    const float* bl = (const float*)d_in[4];
    const float* Wk = (const float*)d_in[5];
    const float* bk = (const float*)d_in[6];
    const float* Wv = (const float*)d_in[7];
    const float* bv = (const float*)d_in[8];
    const float* Wo = (const float*)d_in[9];
    const float* bo = (const float*)d_in[10];
    float* out = (float*)d_out;

    bf16 *xh, *xl, *wqh, *wql, *wlh, *wll, *wkh, *wkl, *wvh, *wvl, *woh, *wol;
    bf16 *lath, *latl, *qh, *ql, *kh, *kl, *vth, *vtl, *ath, *atl;
    cudaGetSymbolAddress((void**)&xh, g_xh);   cudaGetSymbolAddress((void**)&xl, g_xl);
    cudaGetSymbolAddress((void**)&wqh, g_wqh); cudaGetSymbolAddress((void**)&wql, g_wql);
    cudaGetSymbolAddress((void**)&wlh, g_wlh); cudaGetSymbolAddress((void**)&wll, g_wll);
    cudaGetSymbolAddress((void**)&wkh, g_wkh); cudaGetSymbolAddress((void**)&wkl, g_wkl);
    cudaGetSymbolAddress((void**)&wvh, g_wvh); cudaGetSymbolAddress((void**)&wvl, g_wvl);
    cudaGetSymbolAddress((void**)&woh, g_woh); cudaGetSymbolAddress((void**)&wol, g_wol);
    cudaGetSymbolAddress((void**)&lath, g_lath); cudaGetSymbolAddress((void**)&latl, g_latl);
    cudaGetSymbolAddress((void**)&qh, g_qh);   cudaGetSymbolAddress((void**)&ql, g_ql);
    cudaGetSymbolAddress((void**)&kh, g_kh);   cudaGetSymbolAddress((void**)&kl, g_kl);
    cudaGetSymbolAddress((void**)&vth, g_vth); cudaGetSymbolAddress((void**)&vtl, g_vtl);
    cudaGetSymbolAddress((void**)&ath, g_ath); cudaGetSymbolAddress((void**)&atl, g_atl);

    const int SMEM = 81920;
    cudaFuncSetAttribute(mma_gemm<0>, cudaFuncAttributeMaxDynamicSharedMemorySize, SMEM);
    cudaFuncSetAttribute(mma_gemm<1>, cudaFuncAttributeMaxDynamicSharedMemorySize, SMEM);
    cudaFuncSetAttribute(mma_gemm<2>, cudaFuncAttributeMaxDynamicSharedMemorySize, SMEM);
    cudaFuncSetAttribute(mma_gemm<3>, cudaFuncAttributeMaxDynamicSharedMemorySize, SMEM);
    const int FSMEM = 2 * 53248;
    cudaFuncSetAttribute(flash_attn, cudaFuncAttributeMaxDynamicSharedMemorySize, FSMEM);

    const float qscale = 0.08838834764831845f; // 1/sqrt(128)
    dim3 tb(32, 8);

    // operand prep
    split_f4<<<(BT * HID / 4 + 255) / 256, 256>>>(x, xh, xl, BT * HID / 4);
    trans_split<<<dim3(HID / 32, HID / 32, 1), tb>>>(Wq, wqh, wql, HID, HID, 0, 0);
    trans_split<<<dim3(LAT / 32, HID / 32, 1), tb>>>(Wl, wlh, wll, HID, LAT, 0, 0);
    trans_split<<<dim3(DH / 32, LAT / 32, NH), tb>>>(Wk, wkh, wkl, LAT, DH,
        (long long)LAT * DH, (long long)DH * LAT);
    trans_split<<<dim3(DH / 32, LAT / 32, NH), tb>>>(Wv, wvh, wvl, LAT, DH,
        (long long)LAT * DH, (long long)DH * LAT);
    trans_split<<<dim3(HID / 32, HID / 32, 1), tb>>>(Wo, woh, wol, HID, HID, 0, 0);

    // Q = (x@Wq+bq)*scale -> [bh][t][d]
    mma_gemm<2><<<dim3(16, 32, 1), 256, SMEM>>>(xh, xl, wqh, wql, bq,
        nullptr, qh, ql, HID, HID, HID, 0, 0, 0, 0, qscale);
    // latent = x@Wl+bl
    mma_gemm<1><<<dim3(4, 32, 1), 256, SMEM>>>(xh, xl, wlh, wll, bl,
        nullptr, lath, latl, HID, HID, HID, LAT, 0, 0, 0, 1.f);
    // K = latent@Wk'+bk -> [bh][t][d]
    mma_gemm<2><<<dim3(16, 32, 1), 256, SMEM>>>(lath, latl, wkh, wkl, bk,
        nullptr, kh, kl, LAT, LAT, LAT, 0, 0, 0, 0, 1.f);
    // V = latent@Wv'+bv -> [bh][d][t]
    mma_gemm<3><<<dim3(16, 32, 1), 256, SMEM>>>(lath, latl, wvh, wvl, bv,
        nullptr, vth, vtl, LAT, LAT, LAT, 0, 0, 0, 0, 1.f);
    // fused attention -> att hi/lo [b*T+q][h*128+d]
    flash_attn<<<dim3(TT / 128, BH), 256, FSMEM>>>(qh, ql, kh, kl, vth, ath, atl);
    // out = att@Wo+bo
    mma_gemm<0><<<dim3(16, 32, 1), 256, SMEM>>>(ath, atl, woh, wol, bo,
        out, nullptr, nullptr, HID, HID, HID, HID, 0, 0, 0, 1.f);
}

// round 9
// speedup vs baseline: 3.2040x; 1.0001x over previous
#include <cuda_runtime.h>
#include <cuda_fp16.h>
#include <cstdint>

#define HID 2048
#define NH  16
#define DH  128
#define LAT 512
#define TT  2048
#define BT  4096
#define BH  32

typedef __half f16;

// ------------------------- static scratch ----------------------------------
__device__ __align__(256) f16 g_xh[(size_t)BT * HID],  g_xl[(size_t)BT * HID];
__device__ __align__(256) f16 g_wqh[(size_t)HID * HID], g_wql[(size_t)HID * HID];
__device__ __align__(256) f16 g_wlh[(size_t)LAT * HID], g_wll[(size_t)LAT * HID];
__device__ __align__(256) f16 g_wkh[(size_t)HID * LAT], g_wkl[(size_t)HID * LAT];
__device__ __align__(256) f16 g_wvh[(size_t)HID * LAT], g_wvl[(size_t)HID * LAT];
__device__ __align__(256) f16 g_woh[(size_t)HID * HID], g_wol[(size_t)HID * HID];
__device__ __align__(256) f16 g_lath[(size_t)BT * LAT], g_latl[(size_t)BT * LAT];
__device__ __align__(256) f16 g_qh[(size_t)BH * TT * DH], g_ql[(size_t)BH * TT * DH];
__device__ __align__(256) f16 g_kh[(size_t)BH * TT * DH], g_kl[(size_t)BH * TT * DH];
__device__ __align__(256) f16 g_vth[(size_t)BH * TT * DH], g_vtl[(size_t)BH * TT * DH];
__device__ __align__(256) f16 g_ath[(size_t)BT * HID],  g_atl[(size_t)BT * HID];

// ------------------------- helpers ----------------------------------------
__device__ __forceinline__ uint32_t smem_u32(const void* p) {
    uint32_t a;
    asm("{ .reg .u64 t; cvta.to.shared.u64 t, %1; cvt.u32.u64 %0, t; }"
        : "=r"(a) : "l"(p));
    return a;
}
__device__ __forceinline__ float f16r(float x) {
    return __half2float(__float2half_rn(x));
}
__device__ __forceinline__ uint32_t pk2(float a, float b) {
    __half2 t = __floats2half2_rn(a, b);
    return *reinterpret_cast<uint32_t*>(&t);
}
__device__ __forceinline__ void cp16(uint32_t s, const void* g) {
    asm volatile("cp.async.cg.shared.global [%0], [%1], 16;" :: "r"(s), "l"(g));
}
__device__ __forceinline__ void mma16816(float* c, const uint32_t* a,
                                         const uint32_t* b) {
    asm volatile("mma.sync.aligned.m16n8k16.row.col.f32.f16.f16.f32 "
        "{%0,%1,%2,%3}, {%4,%5,%6,%7}, {%8,%9}, {%0,%1,%2,%3};"
        : "+f"(c[0]), "+f"(c[1]), "+f"(c[2]), "+f"(c[3])
        : "r"(a[0]), "r"(a[1]), "r"(a[2]), "r"(a[3]), "r"(b[0]), "r"(b[1]));
}
__device__ __forceinline__ void ldsm4(uint32_t* r, uint32_t addr) {
    asm volatile("ldmatrix.sync.aligned.m8n8.x4.shared.b16 {%0,%1,%2,%3}, [%4];"
        : "=r"(r[0]), "=r"(r[1]), "=r"(r[2]), "=r"(r[3]) : "r"(addr));
}

// ------------------------- conversion kernels ------------------------------
__global__ void split_f4(const float* __restrict__ X, f16* __restrict__ H,
                         f16* __restrict__ L, int n4) {
    int i = blockIdx.x * 256 + threadIdx.x;
    if (i >= n4) return;
    float4 v = ((const float4*)X)[i];
    float ax = f16r(v.x), ay = f16r(v.y), az = f16r(v.z), aw = f16r(v.w);
    uint2 h, l;
    h.x = pk2(ax, ay);             h.y = pk2(az, aw);
    l.x = pk2(v.x - ax, v.y - ay); l.y = pk2(v.z - az, v.w - aw);
    *(uint2*)(H + (size_t)i * 4) = h;
    *(uint2*)(L + (size_t)i * 4) = l;
}

// transpose+split one 32x32 tile: W[K,N] row-major -> out[N,K] hi/lo
__device__ __forceinline__ void trans_tile(const float* __restrict__ W,
                                           f16* __restrict__ OH,
                                           f16* __restrict__ OL,
                                           int K, int N, int n0, int k0,
                                           float tile[32][33],
                                           int tx, int ty) {
#pragma unroll
    for (int j = 0; j < 32; j += 8)
        tile[ty + j][tx] = W[(size_t)(k0 + ty + j) * N + n0 + tx];
    __syncthreads();
#pragma unroll
    for (int j = 0; j < 32; j += 8) {
        float v = tile[tx][ty + j];
        float h = f16r(v);
        size_t idx = (size_t)(n0 + ty + j) * K + k0 + tx;
        OH[idx] = __float2half_rn(h);
        OL[idx] = __float2half_rn(v - h);
    }
}

// all 5 weight transposes in one launch. 11264 blocks of (32,8).
__global__ void trans_all(const float* __restrict__ Wq, const float* __restrict__ Wl,
                          const float* __restrict__ Wk, const float* __restrict__ Wv,
                          const float* __restrict__ Wo,
                          f16* wqh, f16* wql, f16* wlh, f16* wll,
                          f16* wkh, f16* wkl, f16* wvh, f16* wvl,
                          f16* woh, f16* wol) {
    __shared__ float tile[32][33];
    int b = blockIdx.x;
    int tx = threadIdx.x, ty = threadIdx.y;
    if (b < 4096) {            // Wq: K=HID N=HID
        trans_tile(Wq, wqh, wql, HID, HID, (b & 63) * 32, (b >> 6) * 32, tile, tx, ty);
    } else if (b < 5120) {     // Wl: K=HID N=LAT
        b -= 4096;
        trans_tile(Wl, wlh, wll, HID, LAT, (b & 15) * 32, (b >> 4) * 32, tile, tx, ty);
    } else if (b < 6144) {     // Wk: per-head K=LAT N=DH
        b -= 5120;
        int h = b >> 6;
        trans_tile(Wk + (size_t)h * LAT * DH, wkh + (size_t)h * DH * LAT,
                   wkl + (size_t)h * DH * LAT, LAT, DH,
                   (b & 3) * 32, ((b >> 2) & 15) * 32, tile, tx, ty);
    } else if (b < 7168) {     // Wv
        b -= 6144;
        int h = b >> 6;
        trans_tile(Wv + (size_t)h * LAT * DH, wvh + (size_t)h * DH * LAT,
                   wvl + (size_t)h * DH * LAT, LAT, DH,
                   (b & 3) * 32, ((b >> 2) & 15) * 32, tile, tx, ty);
    } else {                   // Wo: K=HID N=HID
        b -= 7168;
        trans_tile(Wo, woh, wol, HID, HID, (b & 63) * 32, (b >> 6) * 32, tile, tx, ty);
    }
}

// ------------------------- HMMA GEMM (projections) -------------------------
// C(128x128) = alpha*((Ah+Al)@(Bh+Bl)^T + bias), 3-MMA hi/lo split, fp16.
// CMODE 0: fp32 out0;  1: split plain;  2: split scatter [bh][t][d];
//       3: split scatter V^T [bh][d][t]
// 3-stage cp.async pipeline, smem = 3 * 40960 = 122880 B.
template<int CMODE>
__global__ void __launch_bounds__(256, 1)
mma_gemm(const f16* __restrict__ Ah, const f16* __restrict__ Al,
         const f16* __restrict__ Bh, const f16* __restrict__ Bl,
         const float* __restrict__ bias, float* __restrict__ out0,
         f16* __restrict__ oh, f16* __restrict__ ol,
         int K, int lda, int ldb, int ldc,
         long long sAz, long long sBz, long long sCz, float alpha)
{
    extern __shared__ char smem[];
    const uint32_t sb = smem_u32(smem);
    const int tid = threadIdx.x, lid = tid & 31, wid = tid >> 5;
    const int wm = wid >> 1, wn = wid & 1;
    const int z = blockIdx.z;
    const int row0 = blockIdx.y << 7, col0 = blockIdx.x << 7;

    const f16* gsrc[4];
    gsrc[0] = Ah + (size_t)z * sAz + (size_t)row0 * lda;
    gsrc[1] = Al + (size_t)z * sAz + (size_t)row0 * lda;
    gsrc[2] = Bh + (size_t)z * sBz + (size_t)col0 * ldb;
    gsrc[3] = Bl + (size_t)z * sBz + (size_t)col0 * ldb;

    const int nt = K >> 5;

    auto load_stage = [&](int buf, int kt) {
#pragma unroll
        for (int i = 0; i < 8; ++i) {
            int cid = tid + (i << 8);
            int q = cid >> 9, idx = cid & 511;
            int row = idx >> 2, c = idx & 3;
            int ld = (q < 2) ? lda : ldb;
            const f16* g = gsrc[q] + (size_t)row * ld + (kt << 5) + (c << 3);
            uint32_t s = sb + (uint32_t)(buf * 4 + q) * 10240u
                            + (uint32_t)row * 80u + ((uint32_t)c << 4);
            cp16(s, g);
        }
        asm volatile("cp.async.commit_group;" ::: "memory");
    };

    float acc[2][8][4];
#pragma unroll
    for (int mi = 0; mi < 2; ++mi)
#pragma unroll
        for (int nj = 0; nj < 8; ++nj)
#pragma unroll
            for (int p = 0; p < 4; ++p) acc[mi][nj][p] = 0.f;

    load_stage(0, 0);
    if (nt > 1) load_stage(1, 1);
    if (nt > 2) load_stage(2, 2);

    const int rowA = lid & 15;
    const int cA   = lid >> 4;
    const int rowB = (lid & 7) + ((lid >> 4) << 3);
    const int cB   = (lid >> 3) & 1;

    for (int t = 0; t < nt; ++t) {
        if (t + 3 <= nt)      asm volatile("cp.async.wait_group 2;" ::: "memory");
        else if (t + 2 <= nt) asm volatile("cp.async.wait_group 1;" ::: "memory");
        else                  asm volatile("cp.async.wait_group 0;" ::: "memory");
        __syncthreads();
        const uint32_t st = sb + (uint32_t)(t % 3) * 40960u;

#pragma unroll
        for (int ks = 0; ks < 2; ++ks) {
            uint32_t a[2][2][4];
#pragma unroll
            for (int mi = 0; mi < 2; ++mi)
#pragma unroll
                for (int hh = 0; hh < 2; ++hh) {
                    uint32_t addr = st + (uint32_t)hh * 10240u
                        + (uint32_t)(wm * 32 + mi * 16 + rowA) * 80u
                        + (uint32_t)(ks * 2 + cA) * 16u;
                    ldsm4(a[mi][hh], addr);
                }
#pragma unroll
            for (int nj = 0; nj < 4; ++nj) {
                uint32_t bh2[4], bl2[4];
                uint32_t ab = st + 2u * 10240u
                    + (uint32_t)(wn * 64 + nj * 16 + rowB) * 80u
                    + (uint32_t)(ks * 2 + cB) * 16u;
                ldsm4(bh2, ab);
                ldsm4(bl2, ab + 10240u);
#pragma unroll
                for (int mi = 0; mi < 2; ++mi)
#pragma unroll
                    for (int p = 0; p < 2; ++p) {
                        float* c = acc[mi][nj * 2 + p];
                        mma16816(c, a[mi][0], bh2 + 2 * p);
                        mma16816(c, a[mi][0], bl2 + 2 * p);
                        mma16816(c, a[mi][1], bh2 + 2 * p);
                    }
            }
        }
        __syncthreads();
        if (t + 3 < nt) load_stage(t % 3, t + 3);
    }

    const int g = lid >> 2, tig = lid & 3;
#pragma unroll
    for (int mi = 0; mi < 2; ++mi)
#pragma unroll
    for (int hh = 0; hh < 2; ++hh) {
        const int m = row0 + wm * 32 + mi * 16 + g + hh * 8;
#pragma unroll
        for (int nj = 0; nj < 8; ++nj) {
            const int n = col0 + wn * 64 + nj * 8 + tig * 2;
            float v0 = acc[mi][nj][hh * 2 + 0];
            float v1 = acc[mi][nj][hh * 2 + 1];
            if (bias) { v0 += bias[n]; v1 += bias[n + 1]; }
            v0 *= alpha; v1 *= alpha;
            if (CMODE == 0) {
                *(float2*)(out0 + (size_t)z * sCz + (size_t)m * ldc + n) =
                    make_float2(v0, v1);
            } else if (CMODE == 3) {
                int b = m >> 11, t2 = m & (TT - 1);
                size_t i0 = ((size_t)((b << 4) + (n >> 7)) * DH + (n & 127)) * TT + t2;
                float h0 = f16r(v0), h1 = f16r(v1);
                oh[i0]      = __float2half_rn(h0);
                ol[i0]      = __float2half_rn(v0 - h0);
                oh[i0 + TT] = __float2half_rn(h1);
                ol[i0 + TT] = __float2half_rn(v1 - h1);
            } else {
                size_t base;
                if (CMODE == 1) {
                    base = (size_t)m * ldc + n;
                } else { // 2
                    int b = m >> 11, t2 = m & (TT - 1);
                    base = ((size_t)((b << 4) + (n >> 7)) * TT + t2) * DH + (n & 127);
                }
                float h0 = f16r(v0), h1 = f16r(v1);
                *(uint32_t*)(oh + base) = pk2(h0, h1);
                *(uint32_t*)(ol + base) = pk2(v0 - h0, v1 - h1);
            }
        }
    }
}

// ------------------------- fused flash attention ---------------------------
// CTA: 128 q-rows of one (b,h). 8 warps x 16 q-rows. KV chunks of 64,
// 3-stage cp.async. S = Q@K^T 3-split fp16; P single fp16; O += P@V.
#define BKV  64
#define NCH  (TT / BKV)
#define KROW 272u
#define VROW 144u
#define KLOFF 17408u
#define VOFF  34816u
#define STSTR 53248u

__global__ void __launch_bounds__(256, 1)
flash_attn(const f16* __restrict__ Qh, const f16* __restrict__ Ql,
           const f16* __restrict__ Kh, const f16* __restrict__ Kl,
           const f16* __restrict__ Vt,
           f16* __restrict__ oh, f16* __restrict__ ol)
{
    extern __shared__ char smem[];
    const uint32_t sb = smem_u32(smem);
    const int tid = threadIdx.x, lid = tid & 31, wid = tid >> 5;
    const int bh = blockIdx.y;
    const int q0 = blockIdx.x << 7;

    const f16* qhb = Qh + ((size_t)bh * TT + q0) * DH;
    const f16* qlb = Ql + ((size_t)bh * TT + q0) * DH;
    const f16* khb = Kh + (size_t)bh * TT * DH;
    const f16* klb = Kl + (size_t)bh * TT * DH;
    const f16* vtb = Vt + (size_t)bh * DH * TT;

    // ---- stage Q (hi in stage0 area, lo in stage1 area) ----
#pragma unroll
    for (int j = 0; j < 8; ++j) {
        int cid = tid + (j << 8);
        int row = cid >> 4, c = cid & 15;
        cp16(sb + (uint32_t)row * KROW + ((uint32_t)c << 4),
             qhb + (size_t)row * DH + (c << 3));
        cp16(sb + STSTR + (uint32_t)row * KROW + ((uint32_t)c << 4),
             qlb + (size_t)row * DH + (c << 3));
    }
    asm volatile("cp.async.commit_group;" ::: "memory");
    asm volatile("cp.async.wait_group 0;" ::: "memory");
    __syncthreads();

    const int rowA = lid & 15, cA = lid >> 4;
    const int rowB = (lid & 7) + ((lid >> 4) << 3), cB = (lid >> 3) & 1;

    uint32_t qfh[8][4], qfl[8][4];
#pragma unroll
    for (int kd = 0; kd < 8; ++kd) {
        uint32_t addr = sb + (uint32_t)(wid * 16 + rowA) * KROW
                           + (uint32_t)(kd * 32 + cA * 16);
        ldsm4(qfh[kd], addr);
        ldsm4(qfl[kd], addr + STSTR);
    }
    __syncthreads();

    auto load_kv = [&](int buf, int i) {
        uint32_t s0 = sb + (uint32_t)buf * STSTR;
#pragma unroll
        for (int j = 0; j < 4; ++j) {
            int cid = tid + (j << 8);
            int row = cid >> 4, c = cid & 15;
            size_t go = (size_t)(i * BKV + row) * DH + (c << 3);
            cp16(s0 + (uint32_t)row * KROW + ((uint32_t)c << 4), khb + go);
            cp16(s0 + KLOFF + (uint32_t)row * KROW + ((uint32_t)c << 4), klb + go);
        }
#pragma unroll
        for (int j = 0; j < 4; ++j) {
            int cid = tid + (j << 8);
            int row = cid >> 3, c = cid & 7;
            cp16(s0 + VOFF + (uint32_t)row * VROW + ((uint32_t)c << 4),
                 vtb + (size_t)row * TT + i * BKV + (c << 3));
        }
        asm volatile("cp.async.commit_group;" ::: "memory");
    };

    float o[16][4];
#pragma unroll
    for (int dj = 0; dj < 16; ++dj)
#pragma unroll
        for (int p = 0; p < 4; ++p) o[dj][p] = 0.f;
    float m0 = -1e30f, m1 = -1e30f, l0 = 0.f, l1 = 0.f;

    load_kv(0, 0);
    load_kv(1, 1);
    load_kv(2, 2);

    for (int i = 0; i < NCH; ++i) {
        if (i + 3 <= NCH)      asm volatile("cp.async.wait_group 2;" ::: "memory");
        else if (i + 2 <= NCH) asm volatile("cp.async.wait_group 1;" ::: "memory");
        else                   asm volatile("cp.async.wait_group 0;" ::: "memory");
        __syncthreads();
        const uint32_t st = sb + (uint32_t)(i % 3) * STSTR;

        // ---- S = Q @ K^T (3-split) ----
        float s[8][4];
#pragma unroll
        for (int nj = 0; nj < 8; ++nj)
#pragma unroll
            for (int p = 0; p < 4; ++p) s[nj][p] = 0.f;
#pragma unroll
        for (int kd = 0; kd < 8; ++kd) {
#pragma unroll
            for (int g2 = 0; g2 < 4; ++g2) {
                uint32_t kf[4], kfl[4];
                uint32_t ab = st + (uint32_t)(g2 * 16 + rowB) * KROW
                                 + (uint32_t)(kd * 32 + cB * 16);
                ldsm4(kf, ab);
                ldsm4(kfl, ab + KLOFF);
#pragma unroll
                for (int p = 0; p < 2; ++p) {
                    float* c = s[g2 * 2 + p];
                    mma16816(c, qfh[kd], kf + 2 * p);
                    mma16816(c, qfh[kd], kfl + 2 * p);
                    mma16816(c, qfl[kd], kf + 2 * p);
                }
            }
        }

        // ---- online softmax ----
        float mx0 = s[0][0], mx1 = s[0][2];
#pragma unroll
        for (int nj = 0; nj < 8; ++nj) {
            mx0 = fmaxf(mx0, fmaxf(s[nj][0], s[nj][1]));
            mx1 = fmaxf(mx1, fmaxf(s[nj][2], s[nj][3]));
        }
        mx0 = fmaxf(mx0, __shfl_xor_sync(~0u, mx0, 1));
        mx0 = fmaxf(mx0, __shfl_xor_sync(~0u, mx0, 2));
        mx1 = fmaxf(mx1, __shfl_xor_sync(~0u, mx1, 1));
        mx1 = fmaxf(mx1, __shfl_xor_sync(~0u, mx1, 2));
        float mn0 = fmaxf(m0, mx0), mn1 = fmaxf(m1, mx1);
        float es0 = __expf(m0 - mn0), es1 = __expf(m1 - mn1);
        m0 = mn0; m1 = mn1;
        l0 *= es0; l1 *= es1;
#pragma unroll
        for (int dj = 0; dj < 16; ++dj) {
            o[dj][0] *= es0; o[dj][1] *= es0;
            o[dj][2] *= es1; o[dj][3] *= es1;
        }
        float sum0 = 0.f, sum1 = 0.f;
#pragma unroll
        for (int nj = 0; nj < 8; ++nj) {
            s[nj][0] = __expf(s[nj][0] - m0);
            s[nj][1] = __expf(s[nj][1] - m0);
            s[nj][2] = __expf(s[nj][2] - m1);
            s[nj][3] = __expf(s[nj][3] - m1);
            sum0 += s[nj][0] + s[nj][1];
            sum1 += s[nj][2] + s[nj][3];
        }
        sum0 += __shfl_xor_sync(~0u, sum0, 1);
        sum0 += __shfl_xor_sync(~0u, sum0, 2);
        sum1 += __shfl_xor_sync(~0u, sum1, 1);
        sum1 += __shfl_xor_sync(~0u, sum1, 2);
        l0 += sum0; l1 += sum1;

        // ---- pack P (acc layout == A-fragment layout) ----
        uint32_t ap[4][4];
#pragma unroll
        for (int kt = 0; kt < 4; ++kt) {
            ap[kt][0] = pk2(s[2 * kt][0],     s[2 * kt][1]);
            ap[kt][1] = pk2(s[2 * kt][2],     s[2 * kt][3]);
            ap[kt][2] = pk2(s[2 * kt + 1][0], s[2 * kt + 1][1]);
            ap[kt][3] = pk2(s[2 * kt + 1][2], s[2 * kt + 1][3]);
        }

        // ---- O += P @ V ----
#pragma unroll
        for (int kt = 0; kt < 4; ++kt) {
#pragma unroll
            for (int dg = 0; dg < 8; ++dg) {
                uint32_t vf[4];
                uint32_t ab = st + VOFF + (uint32_t)(dg * 16 + rowB) * VROW
                                 + (uint32_t)(kt * 32 + cB * 16);
                ldsm4(vf, ab);
                mma16816(o[dg * 2 + 0], ap[kt], vf);
                mma16816(o[dg * 2 + 1], ap[kt], vf + 2);
            }
        }
        __syncthreads();
        if (i + 3 < NCH) load_kv(i % 3, i + 3);
    }

    // ---- epilogue ----
    float inv0 = 1.f / l0, inv1 = 1.f / l1;
    const int b = bh >> 4, h = bh & 15;
    const int g = lid >> 2, tig = lid & 3;
    const int mrow = q0 + wid * 16 + g;
#pragma unroll
    for (int dj = 0; dj < 16; ++dj) {
        int n = (h << 7) + dj * 8 + tig * 2;
        float v0 = o[dj][0] * inv0, v1 = o[dj][1] * inv0;
        float v2 = o[dj][2] * inv1, v3 = o[dj][3] * inv1;
        size_t b0 = (size_t)(b * TT + mrow) * HID + n;
        size_t b1 = (size_t)(b * TT + mrow + 8) * HID + n;
        float h0 = f16r(v0), h1 = f16r(v1), h2 = f16r(v2), h3 = f16r(v3);
        *(uint32_t*)(oh + b0) = pk2(h0, h1);
        *(uint32_t*)(ol + b0) = pk2(v0 - h0, v1 - h1);
        *(uint32_t*)(oh + b1) = pk2(h2, h3);
        *(uint32_t*)(ol + b1) = pk2(v2 - h2, v3 - h3);
    }
}

// ------------------------- launcher ----------------------------------------
extern "C" void kernel_launch(void* const* d_in, const int* in_sizes, int n_in,
                              void* d_out, int out_size) {
    const float* x  = (const float*)d_in[0];
    const float* Wq = (const float*)d_in[1];
    const float* bq = (const float*)d_in[2];
    const float* Wl = (const float*)d_in[3];
    const float* bl = (const float*)d_in[4];
    const float* Wk = (const float*)d_in[5];
    const float* bk = (const float*)d_in[6];
    const float* Wv = (const float*)d_in[7];
    const float* bv = (const float*)d_in[8];
    const float* Wo = (const float*)d_in[9];
    const float* bo = (const float*)d_in[10];
    float* out = (float*)d_out;

    f16 *xh, *xl, *wqh, *wql, *wlh, *wll, *wkh, *wkl, *wvh, *wvl, *woh, *wol;
    f16 *lath, *latl, *qh, *ql, *kh, *kl, *vth, *vtl, *ath, *atl;
    cudaGetSymbolAddress((void**)&xh, g_xh);   cudaGetSymbolAddress((void**)&xl, g_xl);
    cudaGetSymbolAddress((void**)&wqh, g_wqh); cudaGetSymbolAddress((void**)&wql, g_wql);
    cudaGetSymbolAddress((void**)&wlh, g_wlh); cudaGetSymbolAddress((void**)&wll, g_wll);
    cudaGetSymbolAddress((void**)&wkh, g_wkh); cudaGetSymbolAddress((void**)&wkl, g_wkl);
    cudaGetSymbolAddress((void**)&wvh, g_wvh); cudaGetSymbolAddress((void**)&wvl, g_wvl);
    cudaGetSymbolAddress((void**)&woh, g_woh); cudaGetSymbolAddress((void**)&wol, g_wol);
    cudaGetSymbolAddress((void**)&lath, g_lath); cudaGetSymbolAddress((void**)&latl, g_latl);
    cudaGetSymbolAddress((void**)&qh, g_qh);   cudaGetSymbolAddress((void**)&ql, g_ql);
    cudaGetSymbolAddress((void**)&kh, g_kh);   cudaGetSymbolAddress((void**)&kl, g_kl);
    cudaGetSymbolAddress((void**)&vth, g_vth); cudaGetSymbolAddress((void**)&vtl, g_vtl);
    cudaGetSymbolAddress((void**)&ath, g_ath); cudaGetSymbolAddress((void**)&atl, g_atl);

    const int SMEM = 3 * 40960;   // 122880
    cudaFuncSetAttribute(mma_gemm<0>, cudaFuncAttributeMaxDynamicSharedMemorySize, SMEM);
    cudaFuncSetAttribute(mma_gemm<1>, cudaFuncAttributeMaxDynamicSharedMemorySize, SMEM);
    cudaFuncSetAttribute(mma_gemm<2>, cudaFuncAttributeMaxDynamicSharedMemorySize, SMEM);
    cudaFuncSetAttribute(mma_gemm<3>, cudaFuncAttributeMaxDynamicSharedMemorySize, SMEM);
    const int FSMEM = 3 * 53248;  // 159744
    cudaFuncSetAttribute(flash_attn, cudaFuncAttributeMaxDynamicSharedMemorySize, FSMEM);

    const float qscale = 0.08838834764831845f; // 1/sqrt(128)

    // launch 0: split x
    split_f4<<<(BT * HID / 4 + 255) / 256, 256>>>(x, xh, xl, BT * HID / 4);
    // launch 1: all weight transposes
    trans_all<<<11264, dim3(32, 8)>>>(Wq, Wl, Wk, Wv, Wo,
        wqh, wql, wlh, wll, wkh, wkl, wvh, wvl, woh, wol);

    // launch 2: Q = (x@Wq+bq)*scale -> [bh][t][d]
    mma_gemm<2><<<dim3(16, 32, 1), 256, SMEM>>>(xh, xl, wqh, wql, bq,
        nullptr, qh, ql, HID, HID, HID, 0, 0, 0, 0, qscale);
    // launch 3: latent = x@Wl+bl
    mma_gemm<1><<<dim3(4, 32, 1), 256, SMEM>>>(xh, xl, wlh, wll, bl,
        nullptr, lath, latl, HID, HID, HID, LAT, 0, 0, 0, 1.f);
    // launch 4: K = latent@Wk'+bk -> [bh][t][d]
    mma_gemm<2><<<dim3(16, 32, 1), 256, SMEM>>>(lath, latl, wkh, wkl, bk,
        nullptr, kh, kl, LAT, LAT, LAT, 0, 0, 0, 0, 1.f);
    // launch 5 (ncu-profiled): V = latent@Wv'+bv -> [bh][d][t]
    mma_gemm<3><<<dim3(16, 32, 1), 256, SMEM>>>(lath, latl, wvh, wvl, bv,
        nullptr, vth, vtl, LAT, LAT, LAT, 0, 0, 0, 0, 1.f);
    // launch 6: fused attention -> att hi/lo
    flash_attn<<<dim3(TT / 128, BH), 256, FSMEM>>>(qh, ql, kh, kl, vth, ath, atl);
    // launch 7: out = att@Wo+bo
    mma_gemm<0><<<dim3(16, 32, 1), 256, SMEM>>>(ath, atl, woh, wol, bo,
        out, nullptr, nullptr, HID, HID, HID, HID, 0, 0, 0, 1.f);
}

// round 10
// speedup vs baseline: 3.5338x; 1.1029x over previous
#include <cuda_runtime.h>
#include <cuda_fp16.h>
#include <cstdint>

#define HID 2048
#define NH  16
#define DH  128
#define LAT 512
#define TT  2048
#define BT  4096
#define BH  32

typedef __half f16;

// ------------------------- static scratch ----------------------------------
__device__ __align__(256) f16 g_xh[(size_t)BT * HID],  g_xl[(size_t)BT * HID];
__device__ __align__(256) f16 g_wqh[(size_t)HID * HID], g_wql[(size_t)HID * HID];
__device__ __align__(256) f16 g_wlh[(size_t)LAT * HID], g_wll[(size_t)LAT * HID];
__device__ __align__(256) f16 g_wkh[(size_t)HID * LAT], g_wkl[(size_t)HID * LAT];
__device__ __align__(256) f16 g_wvh[(size_t)HID * LAT], g_wvl[(size_t)HID * LAT];
__device__ __align__(256) f16 g_woh[(size_t)HID * HID], g_wol[(size_t)HID * HID];
__device__ __align__(256) f16 g_lath[(size_t)BT * LAT], g_latl[(size_t)BT * LAT];
__device__ __align__(256) f16 g_qh[(size_t)BH * TT * DH], g_ql[(size_t)BH * TT * DH];
__device__ __align__(256) f16 g_kh[(size_t)BH * TT * DH], g_kl[(size_t)BH * TT * DH];
__device__ __align__(256) f16 g_vth[(size_t)BH * TT * DH], g_vtl[(size_t)BH * TT * DH];
__device__ __align__(256) f16 g_ath[(size_t)BT * HID],  g_atl[(size_t)BT * HID];

// ------------------------- helpers ----------------------------------------
__device__ __forceinline__ uint32_t smem_u32(const void* p) {
    uint32_t a;
    asm("{ .reg .u64 t; cvta.to.shared.u64 t, %1; cvt.u32.u64 %0, t; }"
        : "=r"(a) : "l"(p));
    return a;
}
__device__ __forceinline__ float f16r(float x) {
    return __half2float(__float2half_rn(x));
}
__device__ __forceinline__ uint32_t pk2(float a, float b) {
    __half2 t = __floats2half2_rn(a, b);
    return *reinterpret_cast<uint32_t*>(&t);
}
__device__ __forceinline__ void cp16(uint32_t s, const void* g) {
    asm volatile("cp.async.cg.shared.global [%0], [%1], 16;" :: "r"(s), "l"(g));
}
__device__ __forceinline__ void mma16816(float* c, const uint32_t* a,
                                         const uint32_t* b) {
    asm volatile("mma.sync.aligned.m16n8k16.row.col.f32.f16.f16.f32 "
        "{%0,%1,%2,%3}, {%4,%5,%6,%7}, {%8,%9}, {%0,%1,%2,%3};"
        : "+f"(c[0]), "+f"(c[1]), "+f"(c[2]), "+f"(c[3])
        : "r"(a[0]), "r"(a[1]), "r"(a[2]), "r"(a[3]), "r"(b[0]), "r"(b[1]));
}
__device__ __forceinline__ void ldsm4(uint32_t* r, uint32_t addr) {
    asm volatile("ldmatrix.sync.aligned.m8n8.x4.shared.b16 {%0,%1,%2,%3}, [%4];"
        : "=r"(r[0]), "=r"(r[1]), "=r"(r[2]), "=r"(r[3]) : "r"(addr));
}

// ------------------------- conversion kernels ------------------------------
__global__ void split_f4(const float* __restrict__ X, f16* __restrict__ H,
                         f16* __restrict__ L, int n4) {
    int i = blockIdx.x * 256 + threadIdx.x;
    if (i >= n4) return;
    float4 v = ((const float4*)X)[i];
    float ax = f16r(v.x), ay = f16r(v.y), az = f16r(v.z), aw = f16r(v.w);
    uint2 h, l;
    h.x = pk2(ax, ay);             h.y = pk2(az, aw);
    l.x = pk2(v.x - ax, v.y - ay); l.y = pk2(v.z - az, v.w - aw);
    *(uint2*)(H + (size_t)i * 4) = h;
    *(uint2*)(L + (size_t)i * 4) = l;
}

// transpose+split one 32x32 tile: W[K,N] row-major -> out[N,K] hi/lo
__device__ __forceinline__ void trans_tile(const float* __restrict__ W,
                                           f16* __restrict__ OH,
                                           f16* __restrict__ OL,
                                           int K, int N, int n0, int k0,
                                           float tile[32][33],
                                           int tx, int ty) {
#pragma unroll
    for (int j = 0; j < 32; j += 8)
        tile[ty + j][tx] = W[(size_t)(k0 + ty + j) * N + n0 + tx];
    __syncthreads();
#pragma unroll
    for (int j = 0; j < 32; j += 8) {
        float v = tile[tx][ty + j];
        float h = f16r(v);
        size_t idx = (size_t)(n0 + ty + j) * K + k0 + tx;
        OH[idx] = __float2half_rn(h);
        OL[idx] = __float2half_rn(v - h);
    }
}

// all 5 weight transposes in one launch. 11264 blocks of (32,8).
__global__ void trans_all(const float* __restrict__ Wq, const float* __restrict__ Wl,
                          const float* __restrict__ Wk, const float* __restrict__ Wv,
                          const float* __restrict__ Wo,
                          f16* wqh, f16* wql, f16* wlh, f16* wll,
                          f16* wkh, f16* wkl, f16* wvh, f16* wvl,
                          f16* woh, f16* wol) {
    __shared__ float tile[32][33];
    int b = blockIdx.x;
    int tx = threadIdx.x, ty = threadIdx.y;
    if (b < 4096) {            // Wq: K=HID N=HID
        trans_tile(Wq, wqh, wql, HID, HID, (b & 63) * 32, (b >> 6) * 32, tile, tx, ty);
    } else if (b < 5120) {     // Wl: K=HID N=LAT
        b -= 4096;
        trans_tile(Wl, wlh, wll, HID, LAT, (b & 15) * 32, (b >> 4) * 32, tile, tx, ty);
    } else if (b < 6144) {     // Wk: per-head K=LAT N=DH
        b -= 5120;
        int h = b >> 6;
        trans_tile(Wk + (size_t)h * LAT * DH, wkh + (size_t)h * DH * LAT,
                   wkl + (size_t)h * DH * LAT, LAT, DH,
                   (b & 3) * 32, ((b >> 2) & 15) * 32, tile, tx, ty);
    } else if (b < 7168) {     // Wv
        b -= 6144;
        int h = b >> 6;
        trans_tile(Wv + (size_t)h * LAT * DH, wvh + (size_t)h * DH * LAT,
                   wvl + (size_t)h * DH * LAT, LAT, DH,
                   (b & 3) * 32, ((b >> 2) & 15) * 32, tile, tx, ty);
    } else {                   // Wo: K=HID N=HID
        b -= 7168;
        trans_tile(Wo, woh, wol, HID, HID, (b & 63) * 32, (b >> 6) * 32, tile, tx, ty);
    }
}

// ------------------------- HMMA GEMM (projections) -------------------------
// C(128x128) = alpha*((Ah+Al)@(Bh+Bl)^T + bias), 3-MMA hi/lo split, fp16.
// CMODE 0: fp32 out0;  1: split plain;  2: split scatter [bh][t][d];
//       3: split scatter V^T [bh][d][t]
// 2-stage cp.async pipeline, smem = 2*40960 = 81920 B -> 2 CTAs/SM.
template<int CMODE>
__global__ void __launch_bounds__(256, 2)
mma_gemm(const f16* __restrict__ Ah, const f16* __restrict__ Al,
         const f16* __restrict__ Bh, const f16* __restrict__ Bl,
         const float* __restrict__ bias, float* __restrict__ out0,
         f16* __restrict__ oh, f16* __restrict__ ol,
         int K, int lda, int ldb, int ldc,
         long long sAz, long long sBz, long long sCz, float alpha)
{
    extern __shared__ char smem[];
    const uint32_t sb = smem_u32(smem);
    const int tid = threadIdx.x, lid = tid & 31, wid = tid >> 5;
    const int wm = wid >> 1, wn = wid & 1;
    const int z = blockIdx.z;
    const int row0 = blockIdx.y << 7, col0 = blockIdx.x << 7;

    const f16* gsrc[4];
    gsrc[0] = Ah + (size_t)z * sAz + (size_t)row0 * lda;
    gsrc[1] = Al + (size_t)z * sAz + (size_t)row0 * lda;
    gsrc[2] = Bh + (size_t)z * sBz + (size_t)col0 * ldb;
    gsrc[3] = Bl + (size_t)z * sBz + (size_t)col0 * ldb;

    const int nt = K >> 5;

    auto load_stage = [&](int buf, int kt) {
#pragma unroll
        for (int i = 0; i < 8; ++i) {
            int cid = tid + (i << 8);
            int q = cid >> 9, idx = cid & 511;
            int row = idx >> 2, c = idx & 3;
            int ld = (q < 2) ? lda : ldb;
            const f16* g = gsrc[q] + (size_t)row * ld + (kt << 5) + (c << 3);
            uint32_t s = sb + (uint32_t)(buf * 4 + q) * 10240u
                            + (uint32_t)row * 80u + ((uint32_t)c << 4);
            cp16(s, g);
        }
        asm volatile("cp.async.commit_group;" ::: "memory");
    };

    float acc[2][8][4];
#pragma unroll
    for (int mi = 0; mi < 2; ++mi)
#pragma unroll
        for (int nj = 0; nj < 8; ++nj)
#pragma unroll
            for (int p = 0; p < 4; ++p) acc[mi][nj][p] = 0.f;

    load_stage(0, 0);
    if (nt > 1) load_stage(1, 1);

    const int rowA = lid & 15;
    const int cA   = lid >> 4;
    const int rowB = (lid & 7) + ((lid >> 4) << 3);
    const int cB   = (lid >> 3) & 1;

    for (int t = 0; t < nt; ++t) {
        if (t + 1 < nt)
            asm volatile("cp.async.wait_group 1;" ::: "memory");
        else
            asm volatile("cp.async.wait_group 0;" ::: "memory");
        __syncthreads();
        const uint32_t st = sb + (uint32_t)(t & 1) * 40960u;

#pragma unroll
        for (int ks = 0; ks < 2; ++ks) {
            uint32_t a[2][2][4];
#pragma unroll
            for (int mi = 0; mi < 2; ++mi)
#pragma unroll
                for (int hh = 0; hh < 2; ++hh) {
                    uint32_t addr = st + (uint32_t)hh * 10240u
                        + (uint32_t)(wm * 32 + mi * 16 + rowA) * 80u
                        + (uint32_t)(ks * 2 + cA) * 16u;
                    ldsm4(a[mi][hh], addr);
                }
#pragma unroll
            for (int nj = 0; nj < 4; ++nj) {
                uint32_t bh2[4], bl2[4];
                uint32_t ab = st + 2u * 10240u
                    + (uint32_t)(wn * 64 + nj * 16 + rowB) * 80u
                    + (uint32_t)(ks * 2 + cB) * 16u;
                ldsm4(bh2, ab);
                ldsm4(bl2, ab + 10240u);
#pragma unroll
                for (int mi = 0; mi < 2; ++mi)
#pragma unroll
                    for (int p = 0; p < 2; ++p) {
                        float* c = acc[mi][nj * 2 + p];
                        mma16816(c, a[mi][0], bh2 + 2 * p);
                        mma16816(c, a[mi][0], bl2 + 2 * p);
                        mma16816(c, a[mi][1], bh2 + 2 * p);
                    }
            }
        }
        __syncthreads();
        if (t + 2 < nt) load_stage(t & 1, t + 2);
    }

    const int g = lid >> 2, tig = lid & 3;
#pragma unroll
    for (int mi = 0; mi < 2; ++mi)
#pragma unroll
    for (int hh = 0; hh < 2; ++hh) {
        const int m = row0 + wm * 32 + mi * 16 + g + hh * 8;
#pragma unroll
        for (int nj = 0; nj < 8; ++nj) {
            const int n = col0 + wn * 64 + nj * 8 + tig * 2;
            float v0 = acc[mi][nj][hh * 2 + 0];
            float v1 = acc[mi][nj][hh * 2 + 1];
            if (bias) { v0 += bias[n]; v1 += bias[n + 1]; }
            v0 *= alpha; v1 *= alpha;
            if (CMODE == 0) {
                *(float2*)(out0 + (size_t)z * sCz + (size_t)m * ldc + n) =
                    make_float2(v0, v1);
            } else if (CMODE == 3) {
                int b = m >> 11, t2 = m & (TT - 1);
                size_t i0 = ((size_t)((b << 4) + (n >> 7)) * DH + (n & 127)) * TT + t2;
                float h0 = f16r(v0), h1 = f16r(v1);
                oh[i0]      = __float2half_rn(h0);
                ol[i0]      = __float2half_rn(v0 - h0);
                oh[i0 + TT] = __float2half_rn(h1);
                ol[i0 + TT] = __float2half_rn(v1 - h1);
            } else {
                size_t base;
                if (CMODE == 1) {
                    base = (size_t)m * ldc + n;
                } else { // 2
                    int b = m >> 11, t2 = m & (TT - 1);
                    base = ((size_t)((b << 4) + (n >> 7)) * TT + t2) * DH + (n & 127);
                }
                float h0 = f16r(v0), h1 = f16r(v1);
                *(uint32_t*)(oh + base) = pk2(h0, h1);
                *(uint32_t*)(ol + base) = pk2(v0 - h0, v1 - h1);
            }
        }
    }
}

// ------------------------- fused flash attention ---------------------------
// CTA: 128 q-rows of one (b,h). 8 warps x 16 q-rows. KV chunks of 64,
// 3-stage cp.async. S = Q@K^T 3-split fp16; P single fp16; O += P@V.
#define BKV  64
#define NCH  (TT / BKV)
#define KROW 272u
#define VROW 144u
#define KLOFF 17408u
#define VOFF  34816u
#define STSTR 53248u

__global__ void __launch_bounds__(256, 1)
flash_attn(const f16* __restrict__ Qh, const f16* __restrict__ Ql,
           const f16* __restrict__ Kh, const f16* __restrict__ Kl,
           const f16* __restrict__ Vt,
           f16* __restrict__ oh, f16* __restrict__ ol)
{
    extern __shared__ char smem[];
    const uint32_t sb = smem_u32(smem);
    const int tid = threadIdx.x, lid = tid & 31, wid = tid >> 5;
    const int bh = blockIdx.y;
    const int q0 = blockIdx.x << 7;

    const f16* qhb = Qh + ((size_t)bh * TT + q0) * DH;
    const f16* qlb = Ql + ((size_t)bh * TT + q0) * DH;
    const f16* khb = Kh + (size_t)bh * TT * DH;
    const f16* klb = Kl + (size_t)bh * TT * DH;
    const f16* vtb = Vt + (size_t)bh * DH * TT;

    // ---- stage Q (hi in stage0 area, lo in stage1 area) ----
#pragma unroll
    for (int j = 0; j < 8; ++j) {
        int cid = tid + (j << 8);
        int row = cid >> 4, c = cid & 15;
        cp16(sb + (uint32_t)row * KROW + ((uint32_t)c << 4),
             qhb + (size_t)row * DH + (c << 3));
        cp16(sb + STSTR + (uint32_t)row * KROW + ((uint32_t)c << 4),
             qlb + (size_t)row * DH + (c << 3));
    }
    asm volatile("cp.async.commit_group;" ::: "memory");
    asm volatile("cp.async.wait_group 0;" ::: "memory");
    __syncthreads();

    const int rowA = lid & 15, cA = lid >> 4;
    const int rowB = (lid & 7) + ((lid >> 4) << 3), cB = (lid >> 3) & 1;

    uint32_t qfh[8][4], qfl[8][4];
#pragma unroll
    for (int kd = 0; kd < 8; ++kd) {
        uint32_t addr = sb + (uint32_t)(wid * 16 + rowA) * KROW
                           + (uint32_t)(kd * 32 + cA * 16);
        ldsm4(qfh[kd], addr);
        ldsm4(qfl[kd], addr + STSTR);
    }
    __syncthreads();

    auto load_kv = [&](int buf, int i) {
        uint32_t s0 = sb + (uint32_t)buf * STSTR;
#pragma unroll
        for (int j = 0; j < 4; ++j) {
            int cid = tid + (j << 8);
            int row = cid >> 4, c = cid & 15;
            size_t go = (size_t)(i * BKV + row) * DH + (c << 3);
            cp16(s0 + (uint32_t)row * KROW + ((uint32_t)c << 4), khb + go);
            cp16(s0 + KLOFF + (uint32_t)row * KROW + ((uint32_t)c << 4), klb + go);
        }
#pragma unroll
        for (int j = 0; j < 4; ++j) {
            int cid = tid + (j << 8);
            int row = cid >> 3, c = cid & 7;
            cp16(s0 + VOFF + (uint32_t)row * VROW + ((uint32_t)c << 4),
                 vtb + (size_t)row * TT + i * BKV + (c << 3));
        }
        asm volatile("cp.async.commit_group;" ::: "memory");
    };

    float o[16][4];
#pragma unroll
    for (int dj = 0; dj < 16; ++dj)
#pragma unroll
        for (int p = 0; p < 4; ++p) o[dj][p] = 0.f;
    float m0 = -1e30f, m1 = -1e30f, l0 = 0.f, l1 = 0.f;

    load_kv(0, 0);
    load_kv(1, 1);
    load_kv(2, 2);

    for (int i = 0; i < NCH; ++i) {
        if (i + 3 <= NCH)      asm volatile("cp.async.wait_group 2;" ::: "memory");
        else if (i + 2 <= NCH) asm volatile("cp.async.wait_group 1;" ::: "memory");
        else                   asm volatile("cp.async.wait_group 0;" ::: "memory");
        __syncthreads();
        const uint32_t st = sb + (uint32_t)(i % 3) * STSTR;

        // ---- S = Q @ K^T (3-split) ----
        float s[8][4];
#pragma unroll
        for (int nj = 0; nj < 8; ++nj)
#pragma unroll
            for (int p = 0; p < 4; ++p) s[nj][p] = 0.f;
#pragma unroll
        for (int kd = 0; kd < 8; ++kd) {
#pragma unroll
            for (int g2 = 0; g2 < 4; ++g2) {
                uint32_t kf[4], kfl[4];
                uint32_t ab = st + (uint32_t)(g2 * 16 + rowB) * KROW
                                 + (uint32_t)(kd * 32 + cB * 16);
                ldsm4(kf, ab);
                ldsm4(kfl, ab + KLOFF);
#pragma unroll
                for (int p = 0; p < 2; ++p) {
                    float* c = s[g2 * 2 + p];
                    mma16816(c, qfh[kd], kf + 2 * p);
                    mma16816(c, qfh[kd], kfl + 2 * p);
                    mma16816(c, qfl[kd], kf + 2 * p);
                }
            }
        }

        // ---- online softmax ----
        float mx0 = s[0][0], mx1 = s[0][2];
#pragma unroll
        for (int nj = 0; nj < 8; ++nj) {
            mx0 = fmaxf(mx0, fmaxf(s[nj][0], s[nj][1]));
            mx1 = fmaxf(mx1, fmaxf(s[nj][2], s[nj][3]));
        }
        mx0 = fmaxf(mx0, __shfl_xor_sync(~0u, mx0, 1));
        mx0 = fmaxf(mx0, __shfl_xor_sync(~0u, mx0, 2));
        mx1 = fmaxf(mx1, __shfl_xor_sync(~0u, mx1, 1));
        mx1 = fmaxf(mx1, __shfl_xor_sync(~0u, mx1, 2));
        float mn0 = fmaxf(m0, mx0), mn1 = fmaxf(m1, mx1);
        float es0 = __expf(m0 - mn0), es1 = __expf(m1 - mn1);
        m0 = mn0; m1 = mn1;
        l0 *= es0; l1 *= es1;
#pragma unroll
        for (int dj = 0; dj < 16; ++dj) {
            o[dj][0] *= es0; o[dj][1] *= es0;
            o[dj][2] *= es1; o[dj][3] *= es1;
        }
        float sum0 = 0.f, sum1 = 0.f;
#pragma unroll
        for (int nj = 0; nj < 8; ++nj) {
            s[nj][0] = __expf(s[nj][0] - m0);
            s[nj][1] = __expf(s[nj][1] - m0);
            s[nj][2] = __expf(s[nj][2] - m1);
            s[nj][3] = __expf(s[nj][3] - m1);
            sum0 += s[nj][0] + s[nj][1];
            sum1 += s[nj][2] + s[nj][3];
        }
        sum0 += __shfl_xor_sync(~0u, sum0, 1);
        sum0 += __shfl_xor_sync(~0u, sum0, 2);
        sum1 += __shfl_xor_sync(~0u, sum1, 1);
        sum1 += __shfl_xor_sync(~0u, sum1, 2);
        l0 += sum0; l1 += sum1;

        // ---- pack P (acc layout == A-fragment layout) ----
        uint32_t ap[4][4];
#pragma unroll
        for (int kt = 0; kt < 4; ++kt) {
            ap[kt][0] = pk2(s[2 * kt][0],     s[2 * kt][1]);
            ap[kt][1] = pk2(s[2 * kt][2],     s[2 * kt][3]);
            ap[kt][2] = pk2(s[2 * kt + 1][0], s[2 * kt + 1][1]);
            ap[kt][3] = pk2(s[2 * kt + 1][2], s[2 * kt + 1][3]);
        }

        // ---- O += P @ V ----
#pragma unroll
        for (int kt = 0; kt < 4; ++kt) {
#pragma unroll
            for (int dg = 0; dg < 8; ++dg) {
                uint32_t vf[4];
                uint32_t ab = st + VOFF + (uint32_t)(dg * 16 + rowB) * VROW
                                 + (uint32_t)(kt * 32 + cB * 16);
                ldsm4(vf, ab);
                mma16816(o[dg * 2 + 0], ap[kt], vf);
                mma16816(o[dg * 2 + 1], ap[kt], vf + 2);
            }
        }
        __syncthreads();
        if (i + 3 < NCH) load_kv(i % 3, i + 3);
    }

    // ---- epilogue ----
    float inv0 = 1.f / l0, inv1 = 1.f / l1;
    const int b = bh >> 4, h = bh & 15;
    const int g = lid >> 2, tig = lid & 3;
    const int mrow = q0 + wid * 16 + g;
#pragma unroll
    for (int dj = 0; dj < 16; ++dj) {
        int n = (h << 7) + dj * 8 + tig * 2;
        float v0 = o[dj][0] * inv0, v1 = o[dj][1] * inv0;
        float v2 = o[dj][2] * inv1, v3 = o[dj][3] * inv1;
        size_t b0 = (size_t)(b * TT + mrow) * HID + n;
        size_t b1 = (size_t)(b * TT + mrow + 8) * HID + n;
        float h0 = f16r(v0), h1 = f16r(v1), h2 = f16r(v2), h3 = f16r(v3);
        *(uint32_t*)(oh + b0) = pk2(h0, h1);
        *(uint32_t*)(ol + b0) = pk2(v0 - h0, v1 - h1);
        *(uint32_t*)(oh + b1) = pk2(h2, h3);
        *(uint32_t*)(ol + b1) = pk2(v2 - h2, v3 - h3);
    }
}

// ------------------------- launcher ----------------------------------------
extern "C" void kernel_launch(void* const* d_in, const int* in_sizes, int n_in,
                              void* d_out, int out_size) {
    const float* x  = (const float*)d_in[0];
    const float* Wq = (const float*)d_in[1];
    const float* bq = (const float*)d_in[2];
    const float* Wl = (const float*)d_in[3];
    const float* bl = (const float*)d_in[4];
    const float* Wk = (const float*)d_in[5];
    const float* bk = (const float*)d_in[6];
    const float* Wv = (const float*)d_in[7];
    const float* bv = (const float*)d_in[8];
    const float* Wo = (const float*)d_in[9];
    const float* bo = (const float*)d_in[10];
    float* out = (float*)d_out;

    f16 *xh, *xl, *wqh, *wql, *wlh, *wll, *wkh, *wkl, *wvh, *wvl, *woh, *wol;
    f16 *lath, *latl, *qh, *ql, *kh, *kl, *vth, *vtl, *ath, *atl;
    cudaGetSymbolAddress((void**)&xh, g_xh);   cudaGetSymbolAddress((void**)&xl, g_xl);
    cudaGetSymbolAddress((void**)&wqh, g_wqh); cudaGetSymbolAddress((void**)&wql, g_wql);
    cudaGetSymbolAddress((void**)&wlh, g_wlh); cudaGetSymbolAddress((void**)&wll, g_wll);
    cudaGetSymbolAddress((void**)&wkh, g_wkh); cudaGetSymbolAddress((void**)&wkl, g_wkl);
    cudaGetSymbolAddress((void**)&wvh, g_wvh); cudaGetSymbolAddress((void**)&wvl, g_wvl);
    cudaGetSymbolAddress((void**)&woh, g_woh); cudaGetSymbolAddress((void**)&wol, g_wol);
    cudaGetSymbolAddress((void**)&lath, g_lath); cudaGetSymbolAddress((void**)&latl, g_latl);
    cudaGetSymbolAddress((void**)&qh, g_qh);   cudaGetSymbolAddress((void**)&ql, g_ql);
    cudaGetSymbolAddress((void**)&kh, g_kh);   cudaGetSymbolAddress((void**)&kl, g_kl);
    cudaGetSymbolAddress((void**)&vth, g_vth); cudaGetSymbolAddress((void**)&vtl, g_vtl);
    cudaGetSymbolAddress((void**)&ath, g_ath); cudaGetSymbolAddress((void**)&atl, g_atl);

    const int SMEM = 2 * 40960;   // 81920 -> 2 CTAs/SM
    cudaFuncSetAttribute(mma_gemm<0>, cudaFuncAttributeMaxDynamicSharedMemorySize, SMEM);
    cudaFuncSetAttribute(mma_gemm<1>, cudaFuncAttributeMaxDynamicSharedMemorySize, SMEM);
    cudaFuncSetAttribute(mma_gemm<2>, cudaFuncAttributeMaxDynamicSharedMemorySize, SMEM);
    cudaFuncSetAttribute(mma_gemm<3>, cudaFuncAttributeMaxDynamicSharedMemorySize, SMEM);
    const int FSMEM = 3 * 53248;  // 159744
    cudaFuncSetAttribute(flash_attn, cudaFuncAttributeMaxDynamicSharedMemorySize, FSMEM);

    const float qscale = 0.08838834764831845f; // 1/sqrt(128)

    // launch 0: split x
    split_f4<<<(BT * HID / 4 + 255) / 256, 256>>>(x, xh, xl, BT * HID / 4);
    // launch 1: all weight transposes
    trans_all<<<11264, dim3(32, 8)>>>(Wq, Wl, Wk, Wv, Wo,
        wqh, wql, wlh, wll, wkh, wkl, wvh, wvl, woh, wol);

    // launch 2: Q = (x@Wq+bq)*scale -> [bh][t][d]
    mma_gemm<2><<<dim3(16, 32, 1), 256, SMEM>>>(xh, xl, wqh, wql, bq,
        nullptr, qh, ql, HID, HID, HID, 0, 0, 0, 0, qscale);
    // launch 3: latent = x@Wl+bl
    mma_gemm<1><<<dim3(4, 32, 1), 256, SMEM>>>(xh, xl, wlh, wll, bl,
        nullptr, lath, latl, HID, HID, HID, LAT, 0, 0, 0, 1.f);
    // launch 4: K = latent@Wk'+bk -> [bh][t][d]
    mma_gemm<2><<<dim3(16, 32, 1), 256, SMEM>>>(lath, latl, wkh, wkl, bk,
        nullptr, kh, kl, LAT, LAT, LAT, 0, 0, 0, 0, 1.f);
    // launch 5 (ncu-profiled): V = latent@Wv'+bv -> [bh][d][t]
    mma_gemm<3><<<dim3(16, 32, 1), 256, SMEM>>>(lath, latl, wvh, wvl, bv,
        nullptr, vth, vtl, LAT, LAT, LAT, 0, 0, 0, 0, 1.f);
    // launch 6: fused attention -> att hi/lo
    flash_attn<<<dim3(TT / 128, BH), 256, FSMEM>>>(qh, ql, kh, kl, vth, ath, atl);
    // launch 7: out = att@Wo+bo
    mma_gemm<0><<<dim3(16, 32, 1), 256, SMEM>>>(ath, atl, woh, wol, bo,
        out, nullptr, nullptr, HID, HID, HID, HID, 0, 0, 0, 1.f);
}

// round 11
// speedup vs baseline: 3.7397x; 1.0583x over previous
#include <cuda_runtime.h>
#include <cuda_fp16.h>
#include <cstdint>

#define HID 2048
#define NH  16
#define DH  128
#define LAT 512
#define TT  2048
#define BT  4096
#define BH  32

typedef __half f16;

// ------------------------- static scratch ----------------------------------
__device__ __align__(256) f16 g_xh[(size_t)BT * HID],  g_xl[(size_t)BT * HID];
__device__ __align__(256) f16 g_wqh[(size_t)HID * HID], g_wql[(size_t)HID * HID];
__device__ __align__(256) f16 g_wlh[(size_t)LAT * HID], g_wll[(size_t)LAT * HID];
__device__ __align__(256) f16 g_wkh[(size_t)HID * LAT], g_wkl[(size_t)HID * LAT];
__device__ __align__(256) f16 g_wvh[(size_t)HID * LAT], g_wvl[(size_t)HID * LAT];
__device__ __align__(256) f16 g_woh[(size_t)HID * HID], g_wol[(size_t)HID * HID];
__device__ __align__(256) f16 g_lath[(size_t)BT * LAT], g_latl[(size_t)BT * LAT];
__device__ __align__(256) f16 g_qh[(size_t)BH * TT * DH], g_ql[(size_t)BH * TT * DH];
__device__ __align__(256) f16 g_kh[(size_t)BH * TT * DH], g_kl[(size_t)BH * TT * DH];
__device__ __align__(256) f16 g_vth[(size_t)BH * TT * DH], g_vtl[(size_t)BH * TT * DH];
__device__ __align__(256) f16 g_ath[(size_t)BT * HID],  g_atl[(size_t)BT * HID];

// ------------------------- helpers ----------------------------------------
__device__ __forceinline__ uint32_t smem_u32(const void* p) {
    uint32_t a;
    asm("{ .reg .u64 t; cvta.to.shared.u64 t, %1; cvt.u32.u64 %0, t; }"
        : "=r"(a) : "l"(p));
    return a;
}
__device__ __forceinline__ float f16r(float x) {
    return __half2float(__float2half_rn(x));
}
__device__ __forceinline__ uint32_t pk2(float a, float b) {
    __half2 t = __floats2half2_rn(a, b);
    return *reinterpret_cast<uint32_t*>(&t);
}
__device__ __forceinline__ void cp16(uint32_t s, const void* g) {
    asm volatile("cp.async.cg.shared.global [%0], [%1], 16;" :: "r"(s), "l"(g));
}
__device__ __forceinline__ void mma16816(float* c, const uint32_t* a,
                                         const uint32_t* b) {
    asm volatile("mma.sync.aligned.m16n8k16.row.col.f32.f16.f16.f32 "
        "{%0,%1,%2,%3}, {%4,%5,%6,%7}, {%8,%9}, {%0,%1,%2,%3};"
        : "+f"(c[0]), "+f"(c[1]), "+f"(c[2]), "+f"(c[3])
        : "r"(a[0]), "r"(a[1]), "r"(a[2]), "r"(a[3]), "r"(b[0]), "r"(b[1]));
}
__device__ __forceinline__ void ldsm4(uint32_t* r, uint32_t addr) {
    asm volatile("ldmatrix.sync.aligned.m8n8.x4.shared.b16 {%0,%1,%2,%3}, [%4];"
        : "=r"(r[0]), "=r"(r[1]), "=r"(r[2]), "=r"(r[3]) : "r"(addr));
}

// ------------------------- fused prep --------------------------------------
// blocks [0, 8192): split x into hi/lo fp16
// blocks [8192, 19456): 32x32 transpose+split tiles of the 5 weights
__device__ __forceinline__ void trans_tile(const float* __restrict__ W,
                                           f16* __restrict__ OH,
                                           f16* __restrict__ OL,
                                           int K, int N, int n0, int k0,
                                           float tile[32][33],
                                           int tx, int ty) {
#pragma unroll
    for (int j = 0; j < 32; j += 8)
        tile[ty + j][tx] = W[(size_t)(k0 + ty + j) * N + n0 + tx];
    __syncthreads();
#pragma unroll
    for (int j = 0; j < 32; j += 8) {
        float v = tile[tx][ty + j];
        float h = f16r(v);
        size_t idx = (size_t)(n0 + ty + j) * K + k0 + tx;
        OH[idx] = __float2half_rn(h);
        OL[idx] = __float2half_rn(v - h);
    }
}

__global__ void prep_all(const float* __restrict__ X,
                         const float* __restrict__ Wq, const float* __restrict__ Wl,
                         const float* __restrict__ Wk, const float* __restrict__ Wv,
                         const float* __restrict__ Wo,
                         f16* xh, f16* xl,
                         f16* wqh, f16* wql, f16* wlh, f16* wll,
                         f16* wkh, f16* wkl, f16* wvh, f16* wvl,
                         f16* woh, f16* wol) {
    __shared__ float tile[32][33];
    int b = blockIdx.x;
    int tx = threadIdx.x, ty = threadIdx.y;
    if (b < 8192) {            // split x: 8192 blocks x 256 threads x float4
        int i = b * 256 + ty * 32 + tx;
        float4 v = ((const float4*)X)[i];
        float ax = f16r(v.x), ay = f16r(v.y), az = f16r(v.z), aw = f16r(v.w);
        uint2 h, l;
        h.x = pk2(ax, ay);             h.y = pk2(az, aw);
        l.x = pk2(v.x - ax, v.y - ay); l.y = pk2(v.z - az, v.w - aw);
        *(uint2*)(xh + (size_t)i * 4) = h;
        *(uint2*)(xl + (size_t)i * 4) = l;
        return;
    }
    b -= 8192;
    if (b < 4096) {            // Wq
        trans_tile(Wq, wqh, wql, HID, HID, (b & 63) * 32, (b >> 6) * 32, tile, tx, ty);
    } else if (b < 5120) {     // Wl
        b -= 4096;
        trans_tile(Wl, wlh, wll, HID, LAT, (b & 15) * 32, (b >> 4) * 32, tile, tx, ty);
    } else if (b < 6144) {     // Wk per-head
        b -= 5120;
        int h = b >> 6;
        trans_tile(Wk + (size_t)h * LAT * DH, wkh + (size_t)h * DH * LAT,
                   wkl + (size_t)h * DH * LAT, LAT, DH,
                   (b & 3) * 32, ((b >> 2) & 15) * 32, tile, tx, ty);
    } else if (b < 7168) {     // Wv per-head
        b -= 6144;
        int h = b >> 6;
        trans_tile(Wv + (size_t)h * LAT * DH, wvh + (size_t)h * DH * LAT,
                   wvl + (size_t)h * DH * LAT, LAT, DH,
                   (b & 3) * 32, ((b >> 2) & 15) * 32, tile, tx, ty);
    } else {                   // Wo
        b -= 7168;
        trans_tile(Wo, woh, wol, HID, HID, (b & 63) * 32, (b >> 6) * 32, tile, tx, ty);
    }
}

// ------------------------- fused HMMA GEMM ---------------------------------
// Two parts per launch selected by blockIdx.x; K/lda/ldb uniform per launch.
// cmode 0: fp32 out0[m*ldc+n]; 1: split (oh,ol)[m*ldc+n];
//       2: split scatter [bh][t][d]; 3: split scatter V^T [bh][d][t]
struct GP {
    const f16* Bh; const f16* Bl;
    const float* bias;
    float* out0; f16* oh; f16* ol;
    int nx; int cmode; int ldc; float alpha;
};

__global__ void __launch_bounds__(256, 2)
mma_gemm2(const f16* __restrict__ Ah, const f16* __restrict__ Al,
          int K, int lda, int ldb, GP p0, GP p1)
{
    extern __shared__ char smem[];
    const uint32_t sb = smem_u32(smem);
    const int tid = threadIdx.x, lid = tid & 31, wid = tid >> 5;
    const int wm = wid >> 1, wn = wid & 1;

    int bx = blockIdx.x;
    const bool first = bx < p0.nx;
    if (!first) bx -= p0.nx;
    const f16* Bh = first ? p0.Bh : p1.Bh;
    const f16* Bl = first ? p0.Bl : p1.Bl;
    const float* bias = first ? p0.bias : p1.bias;
    float* out0 = first ? p0.out0 : p1.out0;
    f16* oh = first ? p0.oh : p1.oh;
    f16* ol = first ? p0.ol : p1.ol;
    const int cm  = first ? p0.cmode : p1.cmode;
    const int ldc = first ? p0.ldc : p1.ldc;
    const float alpha = first ? p0.alpha : p1.alpha;

    const int row0 = blockIdx.y << 7, col0 = bx << 7;

    const f16* gsrc[4];
    gsrc[0] = Ah + (size_t)row0 * lda;
    gsrc[1] = Al + (size_t)row0 * lda;
    gsrc[2] = Bh + (size_t)col0 * ldb;
    gsrc[3] = Bl + (size_t)col0 * ldb;

    const int nt = K >> 5;

    auto load_stage = [&](int buf, int kt) {
#pragma unroll
        for (int i = 0; i < 8; ++i) {
            int cid = tid + (i << 8);
            int q = cid >> 9, idx = cid & 511;
            int row = idx >> 2, c = idx & 3;
            int ld = (q < 2) ? lda : ldb;
            const f16* g = gsrc[q] + (size_t)row * ld + (kt << 5) + (c << 3);
            uint32_t s = sb + (uint32_t)(buf * 4 + q) * 10240u
                            + (uint32_t)row * 80u + ((uint32_t)c << 4);
            cp16(s, g);
        }
        asm volatile("cp.async.commit_group;" ::: "memory");
    };

    float acc[2][8][4];
#pragma unroll
    for (int mi = 0; mi < 2; ++mi)
#pragma unroll
        for (int nj = 0; nj < 8; ++nj)
#pragma unroll
            for (int p = 0; p < 4; ++p) acc[mi][nj][p] = 0.f;

    load_stage(0, 0);
    if (nt > 1) load_stage(1, 1);

    const int rowA = lid & 15;
    const int cA   = lid >> 4;
    const int rowB = (lid & 7) + ((lid >> 4) << 3);
    const int cB   = (lid >> 3) & 1;

    for (int t = 0; t < nt; ++t) {
        if (t + 1 < nt)
            asm volatile("cp.async.wait_group 1;" ::: "memory");
        else
            asm volatile("cp.async.wait_group 0;" ::: "memory");
        __syncthreads();
        const uint32_t st = sb + (uint32_t)(t & 1) * 40960u;

#pragma unroll
        for (int ks = 0; ks < 2; ++ks) {
            uint32_t a[2][2][4];
#pragma unroll
            for (int mi = 0; mi < 2; ++mi)
#pragma unroll
                for (int hh = 0; hh < 2; ++hh) {
                    uint32_t addr = st + (uint32_t)hh * 10240u
                        + (uint32_t)(wm * 32 + mi * 16 + rowA) * 80u
                        + (uint32_t)(ks * 2 + cA) * 16u;
                    ldsm4(a[mi][hh], addr);
                }
#pragma unroll
            for (int nj = 0; nj < 4; ++nj) {
                uint32_t bh2[4], bl2[4];
                uint32_t ab = st + 2u * 10240u
                    + (uint32_t)(wn * 64 + nj * 16 + rowB) * 80u
                    + (uint32_t)(ks * 2 + cB) * 16u;
                ldsm4(bh2, ab);
                ldsm4(bl2, ab + 10240u);
#pragma unroll
                for (int mi = 0; mi < 2; ++mi)
#pragma unroll
                    for (int p = 0; p < 2; ++p) {
                        float* c = acc[mi][nj * 2 + p];
                        mma16816(c, a[mi][0], bh2 + 2 * p);
                        mma16816(c, a[mi][0], bl2 + 2 * p);
                        mma16816(c, a[mi][1], bh2 + 2 * p);
                    }
            }
        }
        __syncthreads();
        if (t + 2 < nt) load_stage(t & 1, t + 2);
    }

    const int g = lid >> 2, tig = lid & 3;
#pragma unroll
    for (int mi = 0; mi < 2; ++mi)
#pragma unroll
    for (int hh = 0; hh < 2; ++hh) {
        const int m = row0 + wm * 32 + mi * 16 + g + hh * 8;
#pragma unroll
        for (int nj = 0; nj < 8; ++nj) {
            const int n = col0 + wn * 64 + nj * 8 + tig * 2;
            float v0 = acc[mi][nj][hh * 2 + 0];
            float v1 = acc[mi][nj][hh * 2 + 1];
            if (bias) { v0 += bias[n]; v1 += bias[n + 1]; }
            v0 *= alpha; v1 *= alpha;
            if (cm == 0) {
                *(float2*)(out0 + (size_t)m * ldc + n) = make_float2(v0, v1);
            } else if (cm == 3) {
                int b = m >> 11, t2 = m & (TT - 1);
                size_t i0 = ((size_t)((b << 4) + (n >> 7)) * DH + (n & 127)) * TT + t2;
                float h0 = f16r(v0), h1 = f16r(v1);
                oh[i0]      = __float2half_rn(h0);
                ol[i0]      = __float2half_rn(v0 - h0);
                oh[i0 + TT] = __float2half_rn(h1);
                ol[i0 + TT] = __float2half_rn(v1 - h1);
            } else {
                size_t base;
                if (cm == 1) {
                    base = (size_t)m * ldc + n;
                } else { // 2
                    int b = m >> 11, t2 = m & (TT - 1);
                    base = ((size_t)((b << 4) + (n >> 7)) * TT + t2) * DH + (n & 127);
                }
                float h0 = f16r(v0), h1 = f16r(v1);
                *(uint32_t*)(oh + base) = pk2(h0, h1);
                *(uint32_t*)(ol + base) = pk2(v0 - h0, v1 - h1);
            }
        }
    }
}

// ------------------------- fused flash attention ---------------------------
#define BKV  64
#define NCH  (TT / BKV)
#define KROW 272u
#define VROW 144u
#define KLOFF 17408u
#define VOFF  34816u
#define STSTR 53248u

__global__ void __launch_bounds__(256, 1)
flash_attn(const f16* __restrict__ Qh, const f16* __restrict__ Ql,
           const f16* __restrict__ Kh, const f16* __restrict__ Kl,
           const f16* __restrict__ Vt,
           f16* __restrict__ oh, f16* __restrict__ ol)
{
    extern __shared__ char smem[];
    const uint32_t sb = smem_u32(smem);
    const int tid = threadIdx.x, lid = tid & 31, wid = tid >> 5;
    const int bh = blockIdx.y;
    const int q0 = blockIdx.x << 7;

    const f16* qhb = Qh + ((size_t)bh * TT + q0) * DH;
    const f16* qlb = Ql + ((size_t)bh * TT + q0) * DH;
    const f16* khb = Kh + (size_t)bh * TT * DH;
    const f16* klb = Kl + (size_t)bh * TT * DH;
    const f16* vtb = Vt + (size_t)bh * DH * TT;

#pragma unroll
    for (int j = 0; j < 8; ++j) {
        int cid = tid + (j << 8);
        int row = cid >> 4, c = cid & 15;
        cp16(sb + (uint32_t)row * KROW + ((uint32_t)c << 4),
             qhb + (size_t)row * DH + (c << 3));
        cp16(sb + STSTR + (uint32_t)row * KROW + ((uint32_t)c << 4),
             qlb + (size_t)row * DH + (c << 3));
    }
    asm volatile("cp.async.commit_group;" ::: "memory");
    asm volatile("cp.async.wait_group 0;" ::: "memory");
    __syncthreads();

    const int rowA = lid & 15, cA = lid >> 4;
    const int rowB = (lid & 7) + ((lid >> 4) << 3), cB = (lid >> 3) & 1;

    uint32_t qfh[8][4], qfl[8][4];
#pragma unroll
    for (int kd = 0; kd < 8; ++kd) {
        uint32_t addr = sb + (uint32_t)(wid * 16 + rowA) * KROW
                           + (uint32_t)(kd * 32 + cA * 16);
        ldsm4(qfh[kd], addr);
        ldsm4(qfl[kd], addr + STSTR);
    }
    __syncthreads();

    auto load_kv = [&](int buf, int i) {
        uint32_t s0 = sb + (uint32_t)buf * STSTR;
#pragma unroll
        for (int j = 0; j < 4; ++j) {
            int cid = tid + (j << 8);
            int row = cid >> 4, c = cid & 15;
            size_t go = (size_t)(i * BKV + row) * DH + (c << 3);
            cp16(s0 + (uint32_t)row * KROW + ((uint32_t)c << 4), khb + go);
            cp16(s0 + KLOFF + (uint32_t)row * KROW + ((uint32_t)c << 4), klb + go);
        }
#pragma unroll
        for (int j = 0; j < 4; ++j) {
            int cid = tid + (j << 8);
            int row = cid >> 3, c = cid & 7;
            cp16(s0 + VOFF + (uint32_t)row * VROW + ((uint32_t)c << 4),
                 vtb + (size_t)row * TT + i * BKV + (c << 3));
        }
        asm volatile("cp.async.commit_group;" ::: "memory");
    };

    float o[16][4];
#pragma unroll
    for (int dj = 0; dj < 16; ++dj)
#pragma unroll
        for (int p = 0; p < 4; ++p) o[dj][p] = 0.f;
    float m0 = -1e30f, m1 = -1e30f, l0 = 0.f, l1 = 0.f;

    load_kv(0, 0);
    load_kv(1, 1);
    load_kv(2, 2);

    for (int i = 0; i < NCH; ++i) {
        if (i + 3 <= NCH)      asm volatile("cp.async.wait_group 2;" ::: "memory");
        else if (i + 2 <= NCH) asm volatile("cp.async.wait_group 1;" ::: "memory");
        else                   asm volatile("cp.async.wait_group 0;" ::: "memory");
        __syncthreads();
        const uint32_t st = sb + (uint32_t)(i % 3) * STSTR;

        float s[8][4];
#pragma unroll
        for (int nj = 0; nj < 8; ++nj)
#pragma unroll
            for (int p = 0; p < 4; ++p) s[nj][p] = 0.f;
#pragma unroll
        for (int kd = 0; kd < 8; ++kd) {
#pragma unroll
            for (int g2 = 0; g2 < 4; ++g2) {
                uint32_t kf[4], kfl[4];
                uint32_t ab = st + (uint32_t)(g2 * 16 + rowB) * KROW
                                 + (uint32_t)(kd * 32 + cB * 16);
                ldsm4(kf, ab);
                ldsm4(kfl, ab + KLOFF);
#pragma unroll
                for (int p = 0; p < 2; ++p) {
                    float* c = s[g2 * 2 + p];
                    mma16816(c, qfh[kd], kf + 2 * p);
                    mma16816(c, qfh[kd], kfl + 2 * p);
                    mma16816(c, qfl[kd], kf + 2 * p);
                }
            }
        }

        float mx0 = s[0][0], mx1 = s[0][2];
#pragma unroll
        for (int nj = 0; nj < 8; ++nj) {
            mx0 = fmaxf(mx0, fmaxf(s[nj][0], s[nj][1]));
            mx1 = fmaxf(mx1, fmaxf(s[nj][2], s[nj][3]));
        }
        mx0 = fmaxf(mx0, __shfl_xor_sync(~0u, mx0, 1));
        mx0 = fmaxf(mx0, __shfl_xor_sync(~0u, mx0, 2));
        mx1 = fmaxf(mx1, __shfl_xor_sync(~0u, mx1, 1));
        mx1 = fmaxf(mx1, __shfl_xor_sync(~0u, mx1, 2));
        float mn0 = fmaxf(m0, mx0), mn1 = fmaxf(m1, mx1);
        float es0 = __expf(m0 - mn0), es1 = __expf(m1 - mn1);
        m0 = mn0; m1 = mn1;
        l0 *= es0; l1 *= es1;
#pragma unroll
        for (int dj = 0; dj < 16; ++dj) {
            o[dj][0] *= es0; o[dj][1] *= es0;
            o[dj][2] *= es1; o[dj][3] *= es1;
        }
        float sum0 = 0.f, sum1 = 0.f;
#pragma unroll
        for (int nj = 0; nj < 8; ++nj) {
            s[nj][0] = __expf(s[nj][0] - m0);
            s[nj][1] = __expf(s[nj][1] - m0);
            s[nj][2] = __expf(s[nj][2] - m1);
            s[nj][3] = __expf(s[nj][3] - m1);
            sum0 += s[nj][0] + s[nj][1];
            sum1 += s[nj][2] + s[nj][3];
        }
        sum0 += __shfl_xor_sync(~0u, sum0, 1);
        sum0 += __shfl_xor_sync(~0u, sum0, 2);
        sum1 += __shfl_xor_sync(~0u, sum1, 1);
        sum1 += __shfl_xor_sync(~0u, sum1, 2);
        l0 += sum0; l1 += sum1;

        uint32_t ap[4][4];
#pragma unroll
        for (int kt = 0; kt < 4; ++kt) {
            ap[kt][0] = pk2(s[2 * kt][0],     s[2 * kt][1]);
            ap[kt][1] = pk2(s[2 * kt][2],     s[2 * kt][3]);
            ap[kt][2] = pk2(s[2 * kt + 1][0], s[2 * kt + 1][1]);
            ap[kt][3] = pk2(s[2 * kt + 1][2], s[2 * kt + 1][3]);
        }

#pragma unroll
        for (int kt = 0; kt < 4; ++kt) {
#pragma unroll
            for (int dg = 0; dg < 8; ++dg) {
                uint32_t vf[4];
                uint32_t ab = st + VOFF + (uint32_t)(dg * 16 + rowB) * VROW
                                 + (uint32_t)(kt * 32 + cB * 16);
                ldsm4(vf, ab);
                mma16816(o[dg * 2 + 0], ap[kt], vf);
                mma16816(o[dg * 2 + 1], ap[kt], vf + 2);
            }
        }
        __syncthreads();
        if (i + 3 < NCH) load_kv(i % 3, i + 3);
    }

    float inv0 = 1.f / l0, inv1 = 1.f / l1;
    const int b = bh >> 4, h = bh & 15;
    const int g = lid >> 2, tig = lid & 3;
    const int mrow = q0 + wid * 16 + g;
#pragma unroll
    for (int dj = 0; dj < 16; ++dj) {
        int n = (h << 7) + dj * 8 + tig * 2;
        float v0 = o[dj][0] * inv0, v1 = o[dj][1] * inv0;
        float v2 = o[dj][2] * inv1, v3 = o[dj][3] * inv1;
        size_t b0 = (size_t)(b * TT + mrow) * HID + n;
        size_t b1 = (size_t)(b * TT + mrow + 8) * HID + n;
        float h0 = f16r(v0), h1 = f16r(v1), h2 = f16r(v2), h3 = f16r(v3);
        *(uint32_t*)(oh + b0) = pk2(h0, h1);
        *(uint32_t*)(ol + b0) = pk2(v0 - h0, v1 - h1);
        *(uint32_t*)(oh + b1) = pk2(h2, h3);
        *(uint32_t*)(ol + b1) = pk2(v2 - h2, v3 - h3);
    }
}

// ------------------------- launcher ----------------------------------------
extern "C" void kernel_launch(void* const* d_in, const int* in_sizes, int n_in,
                              void* d_out, int out_size) {
    const float* x  = (const float*)d_in[0];
    const float* Wq = (const float*)d_in[1];
    const float* bq = (const float*)d_in[2];
    const float* Wl = (const float*)d_in[3];
    const float* bl = (const float*)d_in[4];
    const float* Wk = (const float*)d_in[5];
    const float* bk = (const float*)d_in[6];
    const float* Wv = (const float*)d_in[7];
    const float* bv = (const float*)d_in[8];
    const float* Wo = (const float*)d_in[9];
    const float* bo = (const float*)d_in[10];
    float* out = (float*)d_out;

    f16 *xh, *xl, *wqh, *wql, *wlh, *wll, *wkh, *wkl, *wvh, *wvl, *woh, *wol;
    f16 *lath, *latl, *qh, *ql, *kh, *kl, *vth, *vtl, *ath, *atl;
    cudaGetSymbolAddress((void**)&xh, g_xh);   cudaGetSymbolAddress((void**)&xl, g_xl);
    cudaGetSymbolAddress((void**)&wqh, g_wqh); cudaGetSymbolAddress((void**)&wql, g_wql);
    cudaGetSymbolAddress((void**)&wlh, g_wlh); cudaGetSymbolAddress((void**)&wll, g_wll);
    cudaGetSymbolAddress((void**)&wkh, g_wkh); cudaGetSymbolAddress((void**)&wkl, g_wkl);
    cudaGetSymbolAddress((void**)&wvh, g_wvh); cudaGetSymbolAddress((void**)&wvl, g_wvl);
    cudaGetSymbolAddress((void**)&woh, g_woh); cudaGetSymbolAddress((void**)&wol, g_wol);
    cudaGetSymbolAddress((void**)&lath, g_lath); cudaGetSymbolAddress((void**)&latl, g_latl);
    cudaGetSymbolAddress((void**)&qh, g_qh);   cudaGetSymbolAddress((void**)&ql, g_ql);
    cudaGetSymbolAddress((void**)&kh, g_kh);   cudaGetSymbolAddress((void**)&kl, g_kl);
    cudaGetSymbolAddress((void**)&vth, g_vth); cudaGetSymbolAddress((void**)&vtl, g_vtl);
    cudaGetSymbolAddress((void**)&ath, g_ath); cudaGetSymbolAddress((void**)&atl, g_atl);

    const int SMEM = 2 * 40960;   // 81920 -> 2 CTAs/SM
    cudaFuncSetAttribute(mma_gemm2, cudaFuncAttributeMaxDynamicSharedMemorySize, SMEM);
    const int FSMEM = 3 * 53248;  // 159744
    cudaFuncSetAttribute(flash_attn, cudaFuncAttributeMaxDynamicSharedMemorySize, FSMEM);

    const float qscale = 0.08838834764831845f; // 1/sqrt(128)

    // launch 0: fused prep (split x + all weight transposes)
    prep_all<<<19456, dim3(32, 8)>>>(x, Wq, Wl, Wk, Wv, Wo,
        xh, xl, wqh, wql, wlh, wll, wkh, wkl, wvh, wvl, woh, wol);

    // launch 1: fused Q-proj (512 CTAs) + latent (128 CTAs)
    {
        GP p0 = {wqh, wql, bq, nullptr, qh, ql, 16, 2, 0, qscale};
        GP p1 = {wlh, wll, bl, nullptr, lath, latl, 4, 1, LAT, 1.f};
        mma_gemm2<<<dim3(20, 32), 256, SMEM>>>(xh, xl, HID, HID, HID, p0, p1);
    }
    // launch 2: fused K-proj + V-proj (1024 CTAs)
    {
        GP p0 = {wkh, wkl, bk, nullptr, kh, kl, 16, 2, 0, 1.f};
        GP p1 = {wvh, wvl, bv, nullptr, vth, vtl, 16, 3, 0, 1.f};
        mma_gemm2<<<dim3(32, 32), 256, SMEM>>>(lath, latl, LAT, LAT, LAT, p0, p1);
    }
    // launch 3 (ncu-profiled slot): fused attention
    flash_attn<<<dim3(TT / 128, BH), 256, FSMEM>>>(qh, ql, kh, kl, vth, ath, atl);
    // launch 4: out = att@Wo+bo
    {
        GP p0 = {woh, wol, bo, out, nullptr, nullptr, 16, 0, HID, 1.f};
        GP p1 = p0; p1.nx = 0;
        mma_gemm2<<<dim3(16, 32), 256, SMEM>>>(ath, atl, HID, HID, HID, p0, p0);
    }
}

// round 14
// speedup vs baseline: 4.0048x; 1.0709x over previous
#include <cuda_runtime.h>
#include <cuda_fp16.h>
#include <cstdint>

#define HID 2048
#define NH  16
#define DH  128
#define LAT 512
#define TT  2048
#define BT  4096
#define BH  32

typedef __half f16;

// ------------------------- static scratch ----------------------------------
__device__ __align__(256) f16 g_xh[(size_t)BT * HID],  g_xl[(size_t)BT * HID];
__device__ __align__(256) f16 g_wqh[(size_t)HID * HID], g_wql[(size_t)HID * HID];
__device__ __align__(256) f16 g_wlh[(size_t)LAT * HID], g_wll[(size_t)LAT * HID];
__device__ __align__(256) f16 g_wkh[(size_t)HID * LAT], g_wkl[(size_t)HID * LAT];
__device__ __align__(256) f16 g_wvh[(size_t)HID * LAT], g_wvl[(size_t)HID * LAT];
__device__ __align__(256) f16 g_woh[(size_t)HID * HID], g_wol[(size_t)HID * HID];
__device__ __align__(256) f16 g_lath[(size_t)BT * LAT], g_latl[(size_t)BT * LAT];
__device__ __align__(256) f16 g_qh[(size_t)BH * TT * DH], g_ql[(size_t)BH * TT * DH];
__device__ __align__(256) f16 g_kh[(size_t)BH * TT * DH], g_kl[(size_t)BH * TT * DH];
__device__ __align__(256) f16 g_vth[(size_t)BH * TT * DH], g_vtl[(size_t)BH * TT * DH];
__device__ __align__(256) f16 g_ath[(size_t)BT * HID],  g_atl[(size_t)BT * HID];

// ------------------------- helpers ----------------------------------------
__device__ __forceinline__ uint32_t smem_u32(const void* p) {
    uint32_t a;
    asm("{ .reg .u64 t; cvta.to.shared.u64 t, %1; cvt.u32.u64 %0, t; }"
        : "=r"(a) : "l"(p));
    return a;
}
__device__ __forceinline__ float f16r(float x) {
    return __half2float(__float2half_rn(x));
}
__device__ __forceinline__ uint32_t pk2(float a, float b) {
    __half2 t = __floats2half2_rn(a, b);
    return *reinterpret_cast<uint32_t*>(&t);
}
__device__ __forceinline__ void cp16(uint32_t s, const void* g) {
    asm volatile("cp.async.cg.shared.global [%0], [%1], 16;" :: "r"(s), "l"(g));
}
__device__ __forceinline__ void mma16816(float* c, const uint32_t* a,
                                         const uint32_t* b) {
    asm volatile("mma.sync.aligned.m16n8k16.row.col.f32.f16.f16.f32 "
        "{%0,%1,%2,%3}, {%4,%5,%6,%7}, {%8,%9}, {%0,%1,%2,%3};"
        : "+f"(c[0]), "+f"(c[1]), "+f"(c[2]), "+f"(c[3])
        : "r"(a[0]), "r"(a[1]), "r"(a[2]), "r"(a[3]), "r"(b[0]), "r"(b[1]));
}
__device__ __forceinline__ void ldsm4(uint32_t* r, uint32_t addr) {
    asm volatile("ldmatrix.sync.aligned.m8n8.x4.shared.b16 {%0,%1,%2,%3}, [%4];"
        : "=r"(r[0]), "=r"(r[1]), "=r"(r[2]), "=r"(r[3]) : "r"(addr));
}

// ------------------------- fused prep --------------------------------------
__device__ __forceinline__ void trans_tile(const float* __restrict__ W,
                                           f16* __restrict__ OH,
                                           f16* __restrict__ OL,
                                           int K, int N, int n0, int k0,
                                           float tile[32][33],
                                           int tx, int ty) {
#pragma unroll
    for (int j = 0; j < 32; j += 8)
        tile[ty + j][tx] = W[(size_t)(k0 + ty + j) * N + n0 + tx];
    __syncthreads();
#pragma unroll
    for (int j = 0; j < 32; j += 8) {
        float v = tile[tx][ty + j];
        float h = f16r(v);
        size_t idx = (size_t)(n0 + ty + j) * K + k0 + tx;
        OH[idx] = __float2half_rn(h);
        OL[idx] = __float2half_rn(v - h);
    }
}

__global__ void prep_all(const float* __restrict__ X,
                         const float* __restrict__ Wq, const float* __restrict__ Wl,
                         const float* __restrict__ Wk, const float* __restrict__ Wv,
                         const float* __restrict__ Wo,
                         f16* xh, f16* xl,
                         f16* wqh, f16* wql, f16* wlh, f16* wll,
                         f16* wkh, f16* wkl, f16* wvh, f16* wvl,
                         f16* woh, f16* wol) {
    __shared__ float tile[32][33];
    int b = blockIdx.x;
    int tx = threadIdx.x, ty = threadIdx.y;
    if (b < 8192) {
        int i = b * 256 + ty * 32 + tx;
        float4 v = ((const float4*)X)[i];
        float ax = f16r(v.x), ay = f16r(v.y), az = f16r(v.z), aw = f16r(v.w);
        uint2 h, l;
        h.x = pk2(ax, ay);             h.y = pk2(az, aw);
        l.x = pk2(v.x - ax, v.y - ay); l.y = pk2(v.z - az, v.w - aw);
        *(uint2*)(xh + (size_t)i * 4) = h;
        *(uint2*)(xl + (size_t)i * 4) = l;
        return;
    }
    b -= 8192;
    if (b < 4096) {
        trans_tile(Wq, wqh, wql, HID, HID, (b & 63) * 32, (b >> 6) * 32, tile, tx, ty);
    } else if (b < 5120) {
        b -= 4096;
        trans_tile(Wl, wlh, wll, HID, LAT, (b & 15) * 32, (b >> 4) * 32, tile, tx, ty);
    } else if (b < 6144) {
        b -= 5120;
        int h = b >> 6;
        trans_tile(Wk + (size_t)h * LAT * DH, wkh + (size_t)h * DH * LAT,
                   wkl + (size_t)h * DH * LAT, LAT, DH,
                   (b & 3) * 32, ((b >> 2) & 15) * 32, tile, tx, ty);
    } else if (b < 7168) {
        b -= 6144;
        int h = b >> 6;
        trans_tile(Wv + (size_t)h * LAT * DH, wvh + (size_t)h * DH * LAT,
                   wvl + (size_t)h * DH * LAT, LAT, DH,
                   (b & 3) * 32, ((b >> 2) & 15) * 32, tile, tx, ty);
    } else {
        b -= 7168;
        trans_tile(Wo, woh, wol, HID, HID, (b & 63) * 32, (b >> 6) * 32, tile, tx, ty);
    }
}

// ------------------------- fused HMMA GEMM ---------------------------------
struct GP {
    const f16* Bh; const f16* Bl;
    const float* bias;
    float* out0; f16* oh; f16* ol;
    int nx; int cmode; int ldc; float alpha;
};

__global__ void __launch_bounds__(256, 2)
mma_gemm2(const f16* __restrict__ Ah, const f16* __restrict__ Al,
          int K, int lda, int ldb, GP p0, GP p1)
{
    extern __shared__ char smem[];
    const uint32_t sb = smem_u32(smem);
    const int tid = threadIdx.x, lid = tid & 31, wid = tid >> 5;
    const int wm = wid >> 1, wn = wid & 1;

    int bx = blockIdx.x;
    const bool first = bx < p0.nx;
    if (!first) bx -= p0.nx;
    const f16* Bh = first ? p0.Bh : p1.Bh;
    const f16* Bl = first ? p0.Bl : p1.Bl;
    const float* bias = first ? p0.bias : p1.bias;
    float* out0 = first ? p0.out0 : p1.out0;
    f16* oh = first ? p0.oh : p1.oh;
    f16* ol = first ? p0.ol : p1.ol;
    const int cm  = first ? p0.cmode : p1.cmode;
    const int ldc = first ? p0.ldc : p1.ldc;
    const float alpha = first ? p0.alpha : p1.alpha;

    const int row0 = blockIdx.y << 7, col0 = bx << 7;

    const f16* gsrc[4];
    gsrc[0] = Ah + (size_t)row0 * lda;
    gsrc[1] = Al + (size_t)row0 * lda;
    gsrc[2] = Bh + (size_t)col0 * ldb;
    gsrc[3] = Bl + (size_t)col0 * ldb;

    const int nt = K >> 5;

    auto load_stage = [&](int buf, int kt) {
#pragma unroll
        for (int i = 0; i < 8; ++i) {
            int cid = tid + (i << 8);
            int q = cid >> 9, idx = cid & 511;
            int row = idx >> 2, c = idx & 3;
            int ld = (q < 2) ? lda : ldb;
            const f16* g = gsrc[q] + (size_t)row * ld + (kt << 5) + (c << 3);
            uint32_t s = sb + (uint32_t)(buf * 4 + q) * 10240u
                            + (uint32_t)row * 80u + ((uint32_t)c << 4);
            cp16(s, g);
        }
        asm volatile("cp.async.commit_group;" ::: "memory");
    };

    float acc[2][8][4];
#pragma unroll
    for (int mi = 0; mi < 2; ++mi)
#pragma unroll
        for (int nj = 0; nj < 8; ++nj)
#pragma unroll
            for (int p = 0; p < 4; ++p) acc[mi][nj][p] = 0.f;

    load_stage(0, 0);
    if (nt > 1) load_stage(1, 1);

    const int rowA = lid & 15;
    const int cA   = lid >> 4;
    const int rowB = (lid & 7) + ((lid >> 4) << 3);
    const int cB   = (lid >> 3) & 1;

    for (int t = 0; t < nt; ++t) {
        if (t + 1 < nt)
            asm volatile("cp.async.wait_group 1;" ::: "memory");
        else
            asm volatile("cp.async.wait_group 0;" ::: "memory");
        __syncthreads();
        const uint32_t st = sb + (uint32_t)(t & 1) * 40960u;

#pragma unroll
        for (int ks = 0; ks < 2; ++ks) {
            uint32_t a[2][2][4];
#pragma unroll
            for (int mi = 0; mi < 2; ++mi)
#pragma unroll
                for (int hh = 0; hh < 2; ++hh) {
                    uint32_t addr = st + (uint32_t)hh * 10240u
                        + (uint32_t)(wm * 32 + mi * 16 + rowA) * 80u
                        + (uint32_t)(ks * 2 + cA) * 16u;
                    ldsm4(a[mi][hh], addr);
                }
#pragma unroll
            for (int nj = 0; nj < 4; ++nj) {
                uint32_t bh2[4], bl2[4];
                uint32_t ab = st + 2u * 10240u
                    + (uint32_t)(wn * 64 + nj * 16 + rowB) * 80u
                    + (uint32_t)(ks * 2 + cB) * 16u;
                ldsm4(bh2, ab);
                ldsm4(bl2, ab + 10240u);
#pragma unroll
                for (int mi = 0; mi < 2; ++mi)
#pragma unroll
                    for (int p = 0; p < 2; ++p) {
                        float* c = acc[mi][nj * 2 + p];
                        mma16816(c, a[mi][0], bh2 + 2 * p);
                        mma16816(c, a[mi][0], bl2 + 2 * p);
                        mma16816(c, a[mi][1], bh2 + 2 * p);
                    }
            }
        }
        __syncthreads();
        if (t + 2 < nt) load_stage(t & 1, t + 2);
    }

    const int g = lid >> 2, tig = lid & 3;
#pragma unroll
    for (int mi = 0; mi < 2; ++mi)
#pragma unroll
    for (int hh = 0; hh < 2; ++hh) {
        const int m = row0 + wm * 32 + mi * 16 + g + hh * 8;
#pragma unroll
        for (int nj = 0; nj < 8; ++nj) {
            const int n = col0 + wn * 64 + nj * 8 + tig * 2;
            float v0 = acc[mi][nj][hh * 2 + 0];
            float v1 = acc[mi][nj][hh * 2 + 1];
            if (bias) { v0 += bias[n]; v1 += bias[n + 1]; }
            v0 *= alpha; v1 *= alpha;
            if (cm == 0) {
                *(float2*)(out0 + (size_t)m * ldc + n) = make_float2(v0, v1);
            } else if (cm == 3) {
                int b = m >> 11, t2 = m & (TT - 1);
                size_t i0 = ((size_t)((b << 4) + (n >> 7)) * DH + (n & 127)) * TT + t2;
                float h0 = f16r(v0), h1 = f16r(v1);
                oh[i0]      = __float2half_rn(h0);
                ol[i0]      = __float2half_rn(v0 - h0);
                oh[i0 + TT] = __float2half_rn(h1);
                ol[i0 + TT] = __float2half_rn(v1 - h1);
            } else {
                size_t base;
                if (cm == 1) {
                    base = (size_t)m * ldc + n;
                } else { // 2
                    int b = m >> 11, t2 = m & (TT - 1);
                    base = ((size_t)((b << 4) + (n >> 7)) * TT + t2) * DH + (n & 127);
                }
                float h0 = f16r(v0), h1 = f16r(v1);
                *(uint32_t*)(oh + base) = pk2(h0, h1);
                *(uint32_t*)(ol + base) = pk2(v0 - h0, v1 - h1);
            }
        }
    }
}

// ------------------------- fused flash attention ---------------------------
// S = (Qh+Ql)@Kh^T (2-MMA split, Kl dropped); P single fp16; O += P@V.
// stage: KH[64x272B] + VT[128x144B] = 35840 B; 3 stages; 1 sync/chunk.
#define BKV  64
#define NCH  (TT / BKV)
#define KROW 272u
#define VROW 144u
#define VOFF  17408u
#define STSTR 35840u

__global__ void __launch_bounds__(256, 1)
flash_attn(const f16* __restrict__ Qh, const f16* __restrict__ Ql,
           const f16* __restrict__ Kh, const f16* __restrict__ Vt,
           f16* __restrict__ oh, f16* __restrict__ ol)
{
    extern __shared__ char smem[];
    const uint32_t sb = smem_u32(smem);
    const int tid = threadIdx.x, lid = tid & 31, wid = tid >> 5;
    const int bh = blockIdx.y;
    const int q0 = blockIdx.x << 7;

    const f16* qhb = Qh + ((size_t)bh * TT + q0) * DH;
    const f16* qlb = Ql + ((size_t)bh * TT + q0) * DH;
    const f16* khb = Kh + (size_t)bh * TT * DH;
    const f16* vtb = Vt + (size_t)bh * DH * TT;

    // ---- stage Q (hi in stage0 area, lo in stage1 area) ----
#pragma unroll
    for (int j = 0; j < 8; ++j) {
        int cid = tid + (j << 8);
        int row = cid >> 4, c = cid & 15;
        cp16(sb + (uint32_t)row * KROW + ((uint32_t)c << 4),
             qhb + (size_t)row * DH + (c << 3));
        cp16(sb + STSTR + (uint32_t)row * KROW + ((uint32_t)c << 4),
             qlb + (size_t)row * DH + (c << 3));
    }
    asm volatile("cp.async.commit_group;" ::: "memory");
    asm volatile("cp.async.wait_group 0;" ::: "memory");
    __syncthreads();

    const int rowA = lid & 15, cA = lid >> 4;
    const int rowB = (lid & 7) + ((lid >> 4) << 3), cB = (lid >> 3) & 1;

    uint32_t qfh[8][4], qfl[8][4];
#pragma unroll
    for (int kd = 0; kd < 8; ++kd) {
        uint32_t addr = sb + (uint32_t)(wid * 16 + rowA) * KROW
                           + (uint32_t)(kd * 32 + cA * 16);
        ldsm4(qfh[kd], addr);
        ldsm4(qfl[kd], addr + STSTR);
    }
    __syncthreads();

    auto load_kv = [&](int buf, int i) {
        uint32_t s0 = sb + (uint32_t)buf * STSTR;
#pragma unroll
        for (int j = 0; j < 4; ++j) {
            int cid = tid + (j << 8);
            int row = cid >> 4, c = cid & 15;
            cp16(s0 + (uint32_t)row * KROW + ((uint32_t)c << 4),
                 khb + (size_t)(i * BKV + row) * DH + (c << 3));
        }
#pragma unroll
        for (int j = 0; j < 4; ++j) {
            int cid = tid + (j << 8);
            int row = cid >> 3, c = cid & 7;
            cp16(s0 + VOFF + (uint32_t)row * VROW + ((uint32_t)c << 4),
                 vtb + (size_t)row * TT + i * BKV + (c << 3));
        }
        asm volatile("cp.async.commit_group;" ::: "memory");
    };

    float o[16][4];
#pragma unroll
    for (int dj = 0; dj < 16; ++dj)
#pragma unroll
        for (int p = 0; p < 4; ++p) o[dj][p] = 0.f;
    float m0 = -1e30f, m1 = -1e30f, l0 = 0.f, l1 = 0.f;

    load_kv(0, 0);
    load_kv(1, 1);

    for (int i = 0; i < NCH; ++i) {
        if (i + 1 < NCH) asm volatile("cp.async.wait_group 1;" ::: "memory");
        else             asm volatile("cp.async.wait_group 0;" ::: "memory");
        __syncthreads();   // all warps done with buffer (i+2)%3 (chunk i-1)
        if (i + 2 < NCH) load_kv((i + 2) % 3, i + 2);
        const uint32_t st = sb + (uint32_t)(i % 3) * STSTR;

        // ---- S = (Qh+Ql) @ Kh^T (2-MMA split) ----
        float s[8][4];
#pragma unroll
        for (int nj = 0; nj < 8; ++nj)
#pragma unroll
            for (int p = 0; p < 4; ++p) s[nj][p] = 0.f;
#pragma unroll
        for (int kd = 0; kd < 8; ++kd) {
#pragma unroll
            for (int g2 = 0; g2 < 4; ++g2) {
                uint32_t kf[4];
                ldsm4(kf, st + (uint32_t)(g2 * 16 + rowB) * KROW
                            + (uint32_t)(kd * 32 + cB * 16));
#pragma unroll
                for (int p = 0; p < 2; ++p) {
                    float* c = s[g2 * 2 + p];
                    mma16816(c, qfh[kd], kf + 2 * p);
                    mma16816(c, qfl[kd], kf + 2 * p);
                }
            }
        }

        // ---- online softmax ----
        float mx0 = s[0][0], mx1 = s[0][2];
#pragma unroll
        for (int nj = 0; nj < 8; ++nj) {
            mx0 = fmaxf(mx0, fmaxf(s[nj][0], s[nj][1]));
            mx1 = fmaxf(mx1, fmaxf(s[nj][2], s[nj][3]));
        }
        mx0 = fmaxf(mx0, __shfl_xor_sync(~0u, mx0, 1));
        mx0 = fmaxf(mx0, __shfl_xor_sync(~0u, mx0, 2));
        mx1 = fmaxf(mx1, __shfl_xor_sync(~0u, mx1, 1));
        mx1 = fmaxf(mx1, __shfl_xor_sync(~0u, mx1, 2));
        float mn0 = fmaxf(m0, mx0), mn1 = fmaxf(m1, mx1);
        float es0 = __expf(m0 - mn0), es1 = __expf(m1 - mn1);
        m0 = mn0; m1 = mn1;
        l0 *= es0; l1 *= es1;
#pragma unroll
        for (int dj = 0; dj < 16; ++dj) {
            o[dj][0] *= es0; o[dj][1] *= es0;
            o[dj][2] *= es1; o[dj][3] *= es1;
        }
        float sum0 = 0.f, sum1 = 0.f;
#pragma unroll
        for (int nj = 0; nj < 8; ++nj) {
            s[nj][0] = __expf(s[nj][0] - m0);
            s[nj][1] = __expf(s[nj][1] - m0);
            s[nj][2] = __expf(s[nj][2] - m1);
            s[nj][3] = __expf(s[nj][3] - m1);
            sum0 += s[nj][0] + s[nj][1];
            sum1 += s[nj][2] + s[nj][3];
        }
        sum0 += __shfl_xor_sync(~0u, sum0, 1);
        sum0 += __shfl_xor_sync(~0u, sum0, 2);
        sum1 += __shfl_xor_sync(~0u, sum1, 1);
        sum1 += __shfl_xor_sync(~0u, sum1, 2);
        l0 += sum0; l1 += sum1;

        // ---- pack P (acc layout == A-fragment layout) ----
        uint32_t ap[4][4];
#pragma unroll
        for (int kt = 0; kt < 4; ++kt) {
            ap[kt][0] = pk2(s[2 * kt][0],     s[2 * kt][1]);
            ap[kt][1] = pk2(s[2 * kt][2],     s[2 * kt][3]);
            ap[kt][2] = pk2(s[2 * kt + 1][0], s[2 * kt + 1][1]);
            ap[kt][3] = pk2(s[2 * kt + 1][2], s[2 * kt + 1][3]);
        }

        // ---- O += P @ V ----
#pragma unroll
        for (int kt = 0; kt < 4; ++kt) {
#pragma unroll
            for (int dg = 0; dg < 8; ++dg) {
                uint32_t vf[4];
                ldsm4(vf, st + VOFF + (uint32_t)(dg * 16 + rowB) * VROW
                               + (uint32_t)(kt * 32 + cB * 16));
                mma16816(o[dg * 2 + 0], ap[kt], vf);
                mma16816(o[dg * 2 + 1], ap[kt], vf + 2);
            }
        }
        // no trailing sync: next iteration's barrier protects buffer reuse
    }

    // ---- epilogue ----
    float inv0 = 1.f / l0, inv1 = 1.f / l1;
    const int b = bh >> 4, h = bh & 15;
    const int g = lid >> 2, tig = lid & 3;
    const int mrow = q0 + wid * 16 + g;
#pragma unroll
    for (int dj = 0; dj < 16; ++dj) {
        int n = (h << 7) + dj * 8 + tig * 2;
        float v0 = o[dj][0] * inv0, v1 = o[dj][1] * inv0;
        float v2 = o[dj][2] * inv1, v3 = o[dj][3] * inv1;
        size_t b0 = (size_t)(b * TT + mrow) * HID + n;
        size_t b1 = (size_t)(b * TT + mrow + 8) * HID + n;
        float h0 = f16r(v0), h1 = f16r(v1), h2 = f16r(v2), h3 = f16r(v3);
        *(uint32_t*)(oh + b0) = pk2(h0, h1);
        *(uint32_t*)(ol + b0) = pk2(v0 - h0, v1 - h1);
        *(uint32_t*)(oh + b1) = pk2(h2, h3);
        *(uint32_t*)(ol + b1) = pk2(v2 - h2, v3 - h3);
    }
}

// ------------------------- launcher ----------------------------------------
extern "C" void kernel_launch(void* const* d_in, const int* in_sizes, int n_in,
                              void* d_out, int out_size) {
    const float* x  = (const float*)d_in[0];
    const float* Wq = (const float*)d_in[1];
    const float* bq = (const float*)d_in[2];
    const float* Wl = (const float*)d_in[3];
    const float* bl = (const float*)d_in[4];
    const float* Wk = (const float*)d_in[5];
    const float* bk = (const float*)d_in[6];
    const float* Wv = (const float*)d_in[7];
    const float* bv = (const float*)d_in[8];
    const float* Wo = (const float*)d_in[9];
    const float* bo = (const float*)d_in[10];
    float* out = (float*)d_out;

    f16 *xh, *xl, *wqh, *wql, *wlh, *wll, *wkh, *wkl, *wvh, *wvl, *woh, *wol;
    f16 *lath, *latl, *qh, *ql, *kh, *kl, *vth, *vtl, *ath, *atl;
    cudaGetSymbolAddress((void**)&xh, g_xh);   cudaGetSymbolAddress((void**)&xl, g_xl);
    cudaGetSymbolAddress((void**)&wqh, g_wqh); cudaGetSymbolAddress((void**)&wql, g_wql);
    cudaGetSymbolAddress((void**)&wlh, g_wlh); cudaGetSymbolAddress((void**)&wll, g_wll);
    cudaGetSymbolAddress((void**)&wkh, g_wkh); cudaGetSymbolAddress((void**)&wkl, g_wkl);
    cudaGetSymbolAddress((void**)&wvh, g_wvh); cudaGetSymbolAddress((void**)&wvl, g_wvl);
    cudaGetSymbolAddress((void**)&woh, g_woh); cudaGetSymbolAddress((void**)&wol, g_wol);
    cudaGetSymbolAddress((void**)&lath, g_lath); cudaGetSymbolAddress((void**)&latl, g_latl);
    cudaGetSymbolAddress((void**)&qh, g_qh);   cudaGetSymbolAddress((void**)&ql, g_ql);
    cudaGetSymbolAddress((void**)&kh, g_kh);   cudaGetSymbolAddress((void**)&kl, g_kl);
    cudaGetSymbolAddress((void**)&vth, g_vth); cudaGetSymbolAddress((void**)&vtl, g_vtl);
    cudaGetSymbolAddress((void**)&ath, g_ath); cudaGetSymbolAddress((void**)&atl, g_atl);

    const int SMEM = 2 * 40960;   // 81920 -> 2 CTAs/SM
    cudaFuncSetAttribute(mma_gemm2, cudaFuncAttributeMaxDynamicSharedMemorySize, SMEM);
    const int FSMEM = 3 * 35840;  // 107520
    cudaFuncSetAttribute(flash_attn, cudaFuncAttributeMaxDynamicSharedMemorySize, FSMEM);

    const float qscale = 0.08838834764831845f; // 1/sqrt(128)

    // launch 0: fused prep (split x + all weight transposes)
    prep_all<<<19456, dim3(32, 8)>>>(x, Wq, Wl, Wk, Wv, Wo,
        xh, xl, wqh, wql, wlh, wll, wkh, wkl, wvh, wvl, woh, wol);

    // launch 1: fused Q-proj (512 CTAs) + latent (128 CTAs)
    {
        GP p0 = {wqh, wql, bq, nullptr, qh, ql, 16, 2, 0, qscale};
        GP p1 = {wlh, wll, bl, nullptr, lath, latl, 4, 1, LAT, 1.f};
        mma_gemm2<<<dim3(20, 32), 256, SMEM>>>(xh, xl, HID, HID, HID, p0, p1);
    }
    // launch 2: fused K-proj + V-proj (1024 CTAs)
    {
        GP p0 = {wkh, wkl, bk, nullptr, kh, kl, 16, 2, 0, 1.f};
        GP p1 = {wvh, wvl, bv, nullptr, vth, vtl, 16, 3, 0, 1.f};
        mma_gemm2<<<dim3(32, 32), 256, SMEM>>>(lath, latl, LAT, LAT, LAT, p0, p1);
    }
    // launch 3 (ncu-profiled slot): fused attention
    flash_attn<<<dim3(TT / 128, BH), 256, FSMEM>>>(qh, ql, kh, vth, ath, atl);
    // launch 4: out = att@Wo+bo
    {
        GP p0 = {woh, wol, bo, out, nullptr, nullptr, 16, 0, HID, 1.f};
        mma_gemm2<<<dim3(16, 32), 256, SMEM>>>(ath, atl, HID, HID, HID, p0, p0);
    }
}

// round 15
// speedup vs baseline: 5.0278x; 1.2555x over previous
#include <cuda_runtime.h>
#include <cuda_fp16.h>
#include <cstdint>

#define HID 2048
#define NH  16
#define DH  128
#define LAT 512
#define TT  2048
#define BT  4096
#define BH  32

typedef __half f16;

// ------------------------- static scratch ----------------------------------
__device__ __align__(256) f16 g_xh[(size_t)BT * HID];
__device__ __align__(256) f16 g_wqh[(size_t)HID * HID], g_wql[(size_t)HID * HID];
__device__ __align__(256) f16 g_wlh[(size_t)LAT * HID], g_wll[(size_t)LAT * HID];
__device__ __align__(256) f16 g_wkh[(size_t)HID * LAT], g_wkl[(size_t)HID * LAT];
__device__ __align__(256) f16 g_wvh[(size_t)HID * LAT], g_wvl[(size_t)HID * LAT];
__device__ __align__(256) f16 g_woh[(size_t)HID * HID], g_wol[(size_t)HID * HID];
__device__ __align__(256) f16 g_lath[(size_t)BT * LAT];
__device__ __align__(256) f16 g_qh[(size_t)BH * TT * DH], g_ql[(size_t)BH * TT * DH];
__device__ __align__(256) f16 g_kh[(size_t)BH * TT * DH];
__device__ __align__(256) f16 g_vth[(size_t)BH * TT * DH];
__device__ __align__(256) f16 g_ath[(size_t)BT * HID];

// ------------------------- helpers ----------------------------------------
__device__ __forceinline__ uint32_t smem_u32(const void* p) {
    uint32_t a;
    asm("{ .reg .u64 t; cvta.to.shared.u64 t, %1; cvt.u32.u64 %0, t; }"
        : "=r"(a) : "l"(p));
    return a;
}
__device__ __forceinline__ float f16r(float x) {
    return __half2float(__float2half_rn(x));
}
__device__ __forceinline__ uint32_t pk2(float a, float b) {
    __half2 t = __floats2half2_rn(a, b);
    return *reinterpret_cast<uint32_t*>(&t);
}
__device__ __forceinline__ void cp16(uint32_t s, const void* g) {
    asm volatile("cp.async.cg.shared.global [%0], [%1], 16;" :: "r"(s), "l"(g));
}
__device__ __forceinline__ void mma16816(float* c, const uint32_t* a,
                                         const uint32_t* b) {
    asm volatile("mma.sync.aligned.m16n8k16.row.col.f32.f16.f16.f32 "
        "{%0,%1,%2,%3}, {%4,%5,%6,%7}, {%8,%9}, {%0,%1,%2,%3};"
        : "+f"(c[0]), "+f"(c[1]), "+f"(c[2]), "+f"(c[3])
        : "r"(a[0]), "r"(a[1]), "r"(a[2]), "r"(a[3]), "r"(b[0]), "r"(b[1]));
}
__device__ __forceinline__ void ldsm4(uint32_t* r, uint32_t addr) {
    asm volatile("ldmatrix.sync.aligned.m8n8.x4.shared.b16 {%0,%1,%2,%3}, [%4];"
        : "=r"(r[0]), "=r"(r[1]), "=r"(r[2]), "=r"(r[3]) : "r"(addr));
}

// ------------------------- fused prep --------------------------------------
__device__ __forceinline__ void trans_tile(const float* __restrict__ W,
                                           f16* __restrict__ OH,
                                           f16* __restrict__ OL,
                                           int K, int N, int n0, int k0,
                                           float tile[32][33],
                                           int tx, int ty) {
#pragma unroll
    for (int j = 0; j < 32; j += 8)
        tile[ty + j][tx] = W[(size_t)(k0 + ty + j) * N + n0 + tx];
    __syncthreads();
#pragma unroll
    for (int j = 0; j < 32; j += 8) {
        float v = tile[tx][ty + j];
        float h = f16r(v);
        size_t idx = (size_t)(n0 + ty + j) * K + k0 + tx;
        OH[idx] = __float2half_rn(h);
        OL[idx] = __float2half_rn(v - h);
    }
}

__global__ void prep_all(const float* __restrict__ X,
                         const float* __restrict__ Wq, const float* __restrict__ Wl,
                         const float* __restrict__ Wk, const float* __restrict__ Wv,
                         const float* __restrict__ Wo,
                         f16* xh,
                         f16* wqh, f16* wql, f16* wlh, f16* wll,
                         f16* wkh, f16* wkl, f16* wvh, f16* wvl,
                         f16* woh, f16* wol) {
    __shared__ float tile[32][33];
    int b = blockIdx.x;
    int tx = threadIdx.x, ty = threadIdx.y;
    if (b < 8192) {            // x -> fp16 (hi only)
        int i = b * 256 + ty * 32 + tx;
        float4 v = ((const float4*)X)[i];
        uint2 h;
        h.x = pk2(v.x, v.y); h.y = pk2(v.z, v.w);
        *(uint2*)(xh + (size_t)i * 4) = h;
        return;
    }
    b -= 8192;
    if (b < 4096) {
        trans_tile(Wq, wqh, wql, HID, HID, (b & 63) * 32, (b >> 6) * 32, tile, tx, ty);
    } else if (b < 5120) {
        b -= 4096;
        trans_tile(Wl, wlh, wll, HID, LAT, (b & 15) * 32, (b >> 4) * 32, tile, tx, ty);
    } else if (b < 6144) {
        b -= 5120;
        int h = b >> 6;
        trans_tile(Wk + (size_t)h * LAT * DH, wkh + (size_t)h * DH * LAT,
                   wkl + (size_t)h * DH * LAT, LAT, DH,
                   (b & 3) * 32, ((b >> 2) & 15) * 32, tile, tx, ty);
    } else if (b < 7168) {
        b -= 6144;
        int h = b >> 6;
        trans_tile(Wv + (size_t)h * LAT * DH, wvh + (size_t)h * DH * LAT,
                   wvl + (size_t)h * DH * LAT, LAT, DH,
                   (b & 3) * 32, ((b >> 2) & 15) * 32, tile, tx, ty);
    } else {
        b -= 7168;
        trans_tile(Wo, woh, wol, HID, HID, (b & 63) * 32, (b >> 6) * 32, tile, tx, ty);
    }
}

// ------------------------- fused HMMA GEMM ---------------------------------
// C(128x128) = alpha*(Ah@(Bh+Bl)^T + bias): 2-MMA split (activation rounded).
// cmode 0: fp32 out0[m*ldc+n]
//       1: fp16 hi-only plain oh[m*ldc+n]
//       2: split scatter both (oh,ol) -> [bh][t][d]   (Q)
//       3: hi-only scatter V^T -> [bh][d][t]          (V)
//       4: hi-only scatter -> [bh][t][d]              (K)
// stage = 3 tiles x 10240 B = 30720; 2 stages; 2 CTAs/SM.
struct GP {
    const f16* Bh; const f16* Bl;
    const float* bias;
    float* out0; f16* oh; f16* ol;
    int nx; int cmode; int ldc; float alpha;
};

__global__ void __launch_bounds__(256, 2)
mma_gemm2(const f16* __restrict__ Ah,
          int K, int lda, int ldb, GP p0, GP p1)
{
    extern __shared__ char smem[];
    const uint32_t sb = smem_u32(smem);
    const int tid = threadIdx.x, lid = tid & 31, wid = tid >> 5;
    const int wm = wid >> 1, wn = wid & 1;

    int bx = blockIdx.x;
    const bool first = bx < p0.nx;
    if (!first) bx -= p0.nx;
    const f16* Bh = first ? p0.Bh : p1.Bh;
    const f16* Bl = first ? p0.Bl : p1.Bl;
    const float* bias = first ? p0.bias : p1.bias;
    float* out0 = first ? p0.out0 : p1.out0;
    f16* oh = first ? p0.oh : p1.oh;
    f16* ol = first ? p0.ol : p1.ol;
    const int cm  = first ? p0.cmode : p1.cmode;
    const int ldc = first ? p0.ldc : p1.ldc;
    const float alpha = first ? p0.alpha : p1.alpha;

    const int row0 = blockIdx.y << 7, col0 = bx << 7;

    const f16* gsrc[3];
    gsrc[0] = Ah + (size_t)row0 * lda;
    gsrc[1] = Bh + (size_t)col0 * ldb;
    gsrc[2] = Bl + (size_t)col0 * ldb;

    const int nt = K >> 5;

    // 1536 16B-chunks per stage, 6 per thread
    auto load_stage = [&](int buf, int kt) {
#pragma unroll
        for (int i = 0; i < 6; ++i) {
            int cid = tid + (i << 8);
            int q = cid >> 9, idx = cid & 511;
            int row = idx >> 2, c = idx & 3;
            int ld = (q == 0) ? lda : ldb;
            const f16* g = gsrc[q] + (size_t)row * ld + (kt << 5) + (c << 3);
            uint32_t s = sb + (uint32_t)(buf * 3 + q) * 10240u
                            + (uint32_t)row * 80u + ((uint32_t)c << 4);
            cp16(s, g);
        }
        asm volatile("cp.async.commit_group;" ::: "memory");
    };

    float acc[2][8][4];
#pragma unroll
    for (int mi = 0; mi < 2; ++mi)
#pragma unroll
        for (int nj = 0; nj < 8; ++nj)
#pragma unroll
            for (int p = 0; p < 4; ++p) acc[mi][nj][p] = 0.f;

    load_stage(0, 0);
    if (nt > 1) load_stage(1, 1);

    const int rowA = lid & 15;
    const int cA   = lid >> 4;
    const int rowB = (lid & 7) + ((lid >> 4) << 3);
    const int cB   = (lid >> 3) & 1;

    for (int t = 0; t < nt; ++t) {
        if (t + 1 < nt)
            asm volatile("cp.async.wait_group 1;" ::: "memory");
        else
            asm volatile("cp.async.wait_group 0;" ::: "memory");
        __syncthreads();
        const uint32_t st = sb + (uint32_t)(t & 1) * 30720u;

#pragma unroll
        for (int ks = 0; ks < 2; ++ks) {
            uint32_t a[2][4];
#pragma unroll
            for (int mi = 0; mi < 2; ++mi) {
                ldsm4(a[mi], st + (uint32_t)(wm * 32 + mi * 16 + rowA) * 80u
                           + (uint32_t)(ks * 2 + cA) * 16u);
            }
#pragma unroll
            for (int nj = 0; nj < 4; ++nj) {
                uint32_t bh2[4], bl2[4];
                uint32_t ab = st + 10240u
                    + (uint32_t)(wn * 64 + nj * 16 + rowB) * 80u
                    + (uint32_t)(ks * 2 + cB) * 16u;
                ldsm4(bh2, ab);
                ldsm4(bl2, ab + 10240u);
#pragma unroll
                for (int mi = 0; mi < 2; ++mi)
#pragma unroll
                    for (int p = 0; p < 2; ++p) {
                        float* c = acc[mi][nj * 2 + p];
                        mma16816(c, a[mi], bh2 + 2 * p);
                        mma16816(c, a[mi], bl2 + 2 * p);
                    }
            }
        }
        __syncthreads();
        if (t + 2 < nt) load_stage(t & 1, t + 2);
    }

    const int g = lid >> 2, tig = lid & 3;
#pragma unroll
    for (int mi = 0; mi < 2; ++mi)
#pragma unroll
    for (int hh = 0; hh < 2; ++hh) {
        const int m = row0 + wm * 32 + mi * 16 + g + hh * 8;
#pragma unroll
        for (int nj = 0; nj < 8; ++nj) {
            const int n = col0 + wn * 64 + nj * 8 + tig * 2;
            float v0 = acc[mi][nj][hh * 2 + 0];
            float v1 = acc[mi][nj][hh * 2 + 1];
            if (bias) { v0 += bias[n]; v1 += bias[n + 1]; }
            v0 *= alpha; v1 *= alpha;
            if (cm == 0) {
                *(float2*)(out0 + (size_t)m * ldc + n) = make_float2(v0, v1);
            } else if (cm == 1) {
                *(uint32_t*)(oh + (size_t)m * ldc + n) = pk2(v0, v1);
            } else if (cm == 2) {
                int b = m >> 11, t2 = m & (TT - 1);
                size_t base = ((size_t)((b << 4) + (n >> 7)) * TT + t2) * DH + (n & 127);
                float h0 = f16r(v0), h1 = f16r(v1);
                *(uint32_t*)(oh + base) = pk2(h0, h1);
                *(uint32_t*)(ol + base) = pk2(v0 - h0, v1 - h1);
            } else if (cm == 3) {
                int b = m >> 11, t2 = m & (TT - 1);
                size_t i0 = ((size_t)((b << 4) + (n >> 7)) * DH + (n & 127)) * TT + t2;
                oh[i0]      = __float2half_rn(v0);
                oh[i0 + TT] = __float2half_rn(v1);
            } else { // 4
                int b = m >> 11, t2 = m & (TT - 1);
                size_t base = ((size_t)((b << 4) + (n >> 7)) * TT + t2) * DH + (n & 127);
                *(uint32_t*)(oh + base) = pk2(v0, v1);
            }
        }
    }
}

// ------------------------- fused flash attention ---------------------------
// S = (Qh+Ql)@Kh^T (2-MMA); P single fp16; O += P@V; output fp16 hi only.
#define BKV  64
#define NCH  (TT / BKV)
#define KROW 272u
#define VROW 144u
#define VOFF  17408u
#define STSTR 35840u

__global__ void __launch_bounds__(256, 1)
flash_attn(const f16* __restrict__ Qh, const f16* __restrict__ Ql,
           const f16* __restrict__ Kh, const f16* __restrict__ Vt,
           f16* __restrict__ oh)
{
    extern __shared__ char smem[];
    const uint32_t sb = smem_u32(smem);
    const int tid = threadIdx.x, lid = tid & 31, wid = tid >> 5;
    const int bh = blockIdx.y;
    const int q0 = blockIdx.x << 7;

    const f16* qhb = Qh + ((size_t)bh * TT + q0) * DH;
    const f16* qlb = Ql + ((size_t)bh * TT + q0) * DH;
    const f16* khb = Kh + (size_t)bh * TT * DH;
    const f16* vtb = Vt + (size_t)bh * DH * TT;

#pragma unroll
    for (int j = 0; j < 8; ++j) {
        int cid = tid + (j << 8);
        int row = cid >> 4, c = cid & 15;
        cp16(sb + (uint32_t)row * KROW + ((uint32_t)c << 4),
             qhb + (size_t)row * DH + (c << 3));
        cp16(sb + STSTR + (uint32_t)row * KROW + ((uint32_t)c << 4),
             qlb + (size_t)row * DH + (c << 3));
    }
    asm volatile("cp.async.commit_group;" ::: "memory");
    asm volatile("cp.async.wait_group 0;" ::: "memory");
    __syncthreads();

    const int rowA = lid & 15, cA = lid >> 4;
    const int rowB = (lid & 7) + ((lid >> 4) << 3), cB = (lid >> 3) & 1;

    uint32_t qfh[8][4], qfl[8][4];
#pragma unroll
    for (int kd = 0; kd < 8; ++kd) {
        uint32_t addr = sb + (uint32_t)(wid * 16 + rowA) * KROW
                           + (uint32_t)(kd * 32 + cA * 16);
        ldsm4(qfh[kd], addr);
        ldsm4(qfl[kd], addr + STSTR);
    }
    __syncthreads();

    auto load_kv = [&](int buf, int i) {
        uint32_t s0 = sb + (uint32_t)buf * STSTR;
#pragma unroll
        for (int j = 0; j < 4; ++j) {
            int cid = tid + (j << 8);
            int row = cid >> 4, c = cid & 15;
            cp16(s0 + (uint32_t)row * KROW + ((uint32_t)c << 4),
                 khb + (size_t)(i * BKV + row) * DH + (c << 3));
        }
#pragma unroll
        for (int j = 0; j < 4; ++j) {
            int cid = tid + (j << 8);
            int row = cid >> 3, c = cid & 7;
            cp16(s0 + VOFF + (uint32_t)row * VROW + ((uint32_t)c << 4),
                 vtb + (size_t)row * TT + i * BKV + (c << 3));
        }
        asm volatile("cp.async.commit_group;" ::: "memory");
    };

    float o[16][4];
#pragma unroll
    for (int dj = 0; dj < 16; ++dj)
#pragma unroll
        for (int p = 0; p < 4; ++p) o[dj][p] = 0.f;
    float m0 = -1e30f, m1 = -1e30f, l0 = 0.f, l1 = 0.f;

    load_kv(0, 0);
    load_kv(1, 1);

    for (int i = 0; i < NCH; ++i) {
        if (i + 1 < NCH) asm volatile("cp.async.wait_group 1;" ::: "memory");
        else             asm volatile("cp.async.wait_group 0;" ::: "memory");
        __syncthreads();
        if (i + 2 < NCH) load_kv((i + 2) % 3, i + 2);
        const uint32_t st = sb + (uint32_t)(i % 3) * STSTR;

        float s[8][4];
#pragma unroll
        for (int nj = 0; nj < 8; ++nj)
#pragma unroll
            for (int p = 0; p < 4; ++p) s[nj][p] = 0.f;
#pragma unroll
        for (int kd = 0; kd < 8; ++kd) {
#pragma unroll
            for (int g2 = 0; g2 < 4; ++g2) {
                uint32_t kf[4];
                ldsm4(kf, st + (uint32_t)(g2 * 16 + rowB) * KROW
                            + (uint32_t)(kd * 32 + cB * 16));
#pragma unroll
                for (int p = 0; p < 2; ++p) {
                    float* c = s[g2 * 2 + p];
                    mma16816(c, qfh[kd], kf + 2 * p);
                    mma16816(c, qfl[kd], kf + 2 * p);
                }
            }
        }

        float mx0 = s[0][0], mx1 = s[0][2];
#pragma unroll
        for (int nj = 0; nj < 8; ++nj) {
            mx0 = fmaxf(mx0, fmaxf(s[nj][0], s[nj][1]));
            mx1 = fmaxf(mx1, fmaxf(s[nj][2], s[nj][3]));
        }
        mx0 = fmaxf(mx0, __shfl_xor_sync(~0u, mx0, 1));
        mx0 = fmaxf(mx0, __shfl_xor_sync(~0u, mx0, 2));
        mx1 = fmaxf(mx1, __shfl_xor_sync(~0u, mx1, 1));
        mx1 = fmaxf(mx1, __shfl_xor_sync(~0u, mx1, 2));
        float mn0 = fmaxf(m0, mx0), mn1 = fmaxf(m1, mx1);
        float es0 = __expf(m0 - mn0), es1 = __expf(m1 - mn1);
        m0 = mn0; m1 = mn1;
        l0 *= es0; l1 *= es1;
#pragma unroll
        for (int dj = 0; dj < 16; ++dj) {
            o[dj][0] *= es0; o[dj][1] *= es0;
            o[dj][2] *= es1; o[dj][3] *= es1;
        }
        float sum0 = 0.f, sum1 = 0.f;
#pragma unroll
        for (int nj = 0; nj < 8; ++nj) {
            s[nj][0] = __expf(s[nj][0] - m0);
            s[nj][1] = __expf(s[nj][1] - m0);
            s[nj][2] = __expf(s[nj][2] - m1);
            s[nj][3] = __expf(s[nj][3] - m1);
            sum0 += s[nj][0] + s[nj][1];
            sum1 += s[nj][2] + s[nj][3];
        }
        sum0 += __shfl_xor_sync(~0u, sum0, 1);
        sum0 += __shfl_xor_sync(~0u, sum0, 2);
        sum1 += __shfl_xor_sync(~0u, sum1, 1);
        sum1 += __shfl_xor_sync(~0u, sum1, 2);
        l0 += sum0; l1 += sum1;

        uint32_t ap[4][4];
#pragma unroll
        for (int kt = 0; kt < 4; ++kt) {
            ap[kt][0] = pk2(s[2 * kt][0],     s[2 * kt][1]);
            ap[kt][1] = pk2(s[2 * kt][2],     s[2 * kt][3]);
            ap[kt][2] = pk2(s[2 * kt + 1][0], s[2 * kt + 1][1]);
            ap[kt][3] = pk2(s[2 * kt + 1][2], s[2 * kt + 1][3]);
        }

#pragma unroll
        for (int kt = 0; kt < 4; ++kt) {
#pragma unroll
            for (int dg = 0; dg < 8; ++dg) {
                uint32_t vf[4];
                ldsm4(vf, st + VOFF + (uint32_t)(dg * 16 + rowB) * VROW
                               + (uint32_t)(kt * 32 + cB * 16));
                mma16816(o[dg * 2 + 0], ap[kt], vf);
                mma16816(o[dg * 2 + 1], ap[kt], vf + 2);
            }
        }
    }

    // ---- epilogue: fp16 hi only ----
    float inv0 = 1.f / l0, inv1 = 1.f / l1;
    const int b = bh >> 4, h = bh & 15;
    const int g = lid >> 2, tig = lid & 3;
    const int mrow = q0 + wid * 16 + g;
#pragma unroll
    for (int dj = 0; dj < 16; ++dj) {
        int n = (h << 7) + dj * 8 + tig * 2;
        size_t b0 = (size_t)(b * TT + mrow) * HID + n;
        size_t b1 = (size_t)(b * TT + mrow + 8) * HID + n;
        *(uint32_t*)(oh + b0) = pk2(o[dj][0] * inv0, o[dj][1] * inv0);
        *(uint32_t*)(oh + b1) = pk2(o[dj][2] * inv1, o[dj][3] * inv1);
    }
}

// ------------------------- launcher ----------------------------------------
extern "C" void kernel_launch(void* const* d_in, const int* in_sizes, int n_in,
                              void* d_out, int out_size) {
    const float* x  = (const float*)d_in[0];
    const float* Wq = (const float*)d_in[1];
    const float* bq = (const float*)d_in[2];
    const float* Wl = (const float*)d_in[3];
    const float* bl = (const float*)d_in[4];
    const float* Wk = (const float*)d_in[5];
    const float* bk = (const float*)d_in[6];
    const float* Wv = (const float*)d_in[7];
    const float* bv = (const float*)d_in[8];
    const float* Wo = (const float*)d_in[9];
    const float* bo = (const float*)d_in[10];
    float* out = (float*)d_out;

    f16 *xh, *wqh, *wql, *wlh, *wll, *wkh, *wkl, *wvh, *wvl, *woh, *wol;
    f16 *lath, *qh, *ql, *kh, *vth, *ath;
    cudaGetSymbolAddress((void**)&xh, g_xh);
    cudaGetSymbolAddress((void**)&wqh, g_wqh); cudaGetSymbolAddress((void**)&wql, g_wql);
    cudaGetSymbolAddress((void**)&wlh, g_wlh); cudaGetSymbolAddress((void**)&wll, g_wll);
    cudaGetSymbolAddress((void**)&wkh, g_wkh); cudaGetSymbolAddress((void**)&wkl, g_wkl);
    cudaGetSymbolAddress((void**)&wvh, g_wvh); cudaGetSymbolAddress((void**)&wvl, g_wvl);
    cudaGetSymbolAddress((void**)&woh, g_woh); cudaGetSymbolAddress((void**)&wol, g_wol);
    cudaGetSymbolAddress((void**)&lath, g_lath);
    cudaGetSymbolAddress((void**)&qh, g_qh);   cudaGetSymbolAddress((void**)&ql, g_ql);
    cudaGetSymbolAddress((void**)&kh, g_kh);
    cudaGetSymbolAddress((void**)&vth, g_vth);
    cudaGetSymbolAddress((void**)&ath, g_ath);

    const int SMEM = 2 * 30720;   // 61440 -> 2 CTAs/SM
    cudaFuncSetAttribute(mma_gemm2, cudaFuncAttributeMaxDynamicSharedMemorySize, SMEM);
    const int FSMEM = 3 * 35840;  // 107520
    cudaFuncSetAttribute(flash_attn, cudaFuncAttributeMaxDynamicSharedMemorySize, FSMEM);

    const float qscale = 0.08838834764831845f; // 1/sqrt(128)

    // launch 0: fused prep (x->fp16 + all weight transposes)
    prep_all<<<19456, dim3(32, 8)>>>(x, Wq, Wl, Wk, Wv, Wo,
        xh, wqh, wql, wlh, wll, wkh, wkl, wvh, wvl, woh, wol);

    // launch 1: fused Q-proj (512 CTAs, split out) + latent (128 CTAs, hi out)
    {
        GP p0 = {wqh, wql, bq, nullptr, qh, ql, 16, 2, 0, qscale};
        GP p1 = {wlh, wll, bl, nullptr, lath, nullptr, 4, 1, LAT, 1.f};
        mma_gemm2<<<dim3(20, 32), 256, SMEM>>>(xh, HID, HID, HID, p0, p1);
    }
    // launch 2: fused K-proj (hi scatter) + V-proj (hi V^T)
    {
        GP p0 = {wkh, wkl, bk, nullptr, kh, nullptr, 16, 4, 0, 1.f};
        GP p1 = {wvh, wvl, bv, nullptr, vth, nullptr, 16, 3, 0, 1.f};
        mma_gemm2<<<dim3(32, 32), 256, SMEM>>>(lath, LAT, LAT, LAT, p0, p1);
    }
    // launch 3 (ncu-profiled slot): fused attention -> ath (fp16)
    flash_attn<<<dim3(TT / 128, BH), 256, FSMEM>>>(qh, ql, kh, vth, ath);
    // launch 4: out = ath@(Woh+Wol) + bo (fp32 out)
    {
        GP p0 = {woh, wol, bo, out, nullptr, nullptr, 16, 0, HID, 1.f};
        mma_gemm2<<<dim3(16, 32), 256, SMEM>>>(ath, HID, HID, HID, p0, p0);
    }
}